// round 8
// baseline (speedup 1.0000x reference)
#include <cuda_runtime.h>
#include <math.h>
#include <stdint.h>

#define BB    2048
#define DD    256
#define HH    512
#define NSLOT 64
#define FEAT  513
#define FEATP 544
#define G4    2048

#define OFF_H      ((size_t)0)
#define OFF_C      ((size_t)1048576)
#define OFF_HMEM   ((size_t)2097152)
#define OFF_SLOTS  ((size_t)3145728)
#define OFF_CUM    ((size_t)36700160)
#define OFF_DELTA  ((size_t)70254592)
#define OFF_FILLED ((size_t)70385664)

// ------------------------------- scratch ------------------------------------
__device__ float g_q[BB * HH];        // q, cols in K-storage order (via Wq row perm)
__device__ float g_kq[BB * DD];
__device__ float g_v[BB * DD];
__device__ int   g_idx[BB];
__device__ float g_bias[G4];
__device__ float g_biaso[G4];
__device__ float g_wihp[(size_t)G4 * FEATP];
__device__ float g_whhp[(size_t)G4 * HH];
__device__ float g_wihop[(size_t)G4 * 768];
__device__ float g_whhop[(size_t)G4 * HH];
__device__ float g_xtf[BB * DD];
__device__ float g_hltf[BB * HH];
__device__ float g_wqtf[HH * DD];
__device__ float g_wkT[DD * HH];
__device__ float g_wvtf[DD * DD];
__device__ float g_mem[(size_t)NSLOT * BB * FEATP];
__device__ float g_xg[(size_t)NSLOT * BB * G4];
__device__ float g_htf0[BB * HH];
__device__ float g_htf1[BB * HH];
__device__ float g_c[BB * HH];
__device__ int   g_fmode;

// K-storage permutation (within each 32-block). MMA slot (g,tg,h) <-> stored pos 8tg+2g+h.
__device__ __forceinline__ int KPERM(int k) {            // true k (0..31) -> stored pos
    return 8 * (k & 3) + 2 * ((k >> 3) & 3) + ((k >> 2) & 1);
}
__device__ __forceinline__ int KPINV(int p) {            // stored pos -> true k
    return 8 * ((p >> 1) & 3) + (p >> 3) + 4 * (p & 1);
}
#define PIF(i) (((i) & ~(size_t)31) | (size_t)KPINV((int)((i) & 31)))

__device__ __forceinline__ uint32_t f2tf(float x) {
    uint32_t r;
    asm("cvt.rna.tf32.f32 %0, %1;" : "=r"(r) : "f"(x));
    return r;
}
__device__ __forceinline__ float tff(float x) { return __uint_as_float(f2tf(x)); }

__device__ __forceinline__ float sigf(float x) { return 1.0f / (1.0f + __expf(-x)); }
__device__ __forceinline__ float tanh_fast(float x) {
    float t = __expf(-2.0f * fabsf(x));
    float r = (1.0f - t) / (1.0f + t);
    return copysignf(r, x);
}

__device__ __forceinline__ int read_filled(const void* p, size_t i, int m) {
    if (m == 0) return ((const float*)p)[i] != 0.0f;
    if (m == 1) return ((const int*)p)[i] != 0;
    if (m == 2) return ((const unsigned char*)p)[i] != 0;
    return ((const unsigned short*)p)[i] != 0;
}

// ----------------------------- PTX helpers ----------------------------------
__device__ __forceinline__ uint32_t smem_u32(const void* p) {
    uint32_t a;
    asm("{ .reg .u64 t; cvta.to.shared.u64 t, %1; cvt.u32.u64 %0, t; }" : "=r"(a) : "l"(p));
    return a;
}
__device__ __forceinline__ void cpasync16(uint32_t dst, const void* src) {
    asm volatile("cp.async.cg.shared.global [%0], [%1], 16;\n" :: "r"(dst), "l"(src));
}
#define CP_COMMIT() asm volatile("cp.async.commit_group;\n" ::: "memory")
#define CP_WAIT1()  asm volatile("cp.async.wait_group 1;\n" ::: "memory")
#define CP_WAIT0()  asm volatile("cp.async.wait_group 0;\n" ::: "memory")

__device__ __forceinline__ void mma8(float* c, const uint32_t* A, const uint32_t* B) {
    asm volatile(
        "mma.sync.aligned.m16n8k8.row.col.f32.tf32.tf32.f32 "
        "{%0,%1,%2,%3}, {%4,%5,%6,%7}, {%8,%9}, {%0,%1,%2,%3};"
        : "+f"(c[0]), "+f"(c[1]), "+f"(c[2]), "+f"(c[3])
        : "r"(A[0]), "r"(A[1]), "r"(A[2]), "r"(A[3]), "r"(B[0]), "r"(B[1]));
}

// ------------------------- tf32 warp-MMA GEMM -------------------------------
// All GEMM operands stored in permuted-K order. C = A[M,K]@W[N,K]^T (+bias)(+Cin).
#define PADK 36
#define TILE_FLOATS 4608
#define BUF_FLOATS  9216
#define SMEM_DYN    (2 * BUF_FLOATS * 4)

struct GArgs {
    int mode, K, lda, ldw, ldc, trunc_out;
    const float *A, *A2, *A3, *W, *W2, *bias, *Cin, *c_in;
    float *C, *c_out, *h_full, *h_tf;
};

__device__ __forceinline__ void load_stage(uint32_t smb, const GArgs& a,
                                           int bm, int bn, int k0, int tid, int buf) {
    const uint32_t base = smb + (uint32_t)buf * BUF_FLOATS * 4;
    const float* Asrc; int lda, ka;
    if (a.mode == 2) {
        if (k0 < 256)      { Asrc = a.A;  lda = 256; ka = k0; }
        else if (k0 < 768) { Asrc = a.A2; lda = 512; ka = k0 - 256; }
        else               { Asrc = a.A3; lda = 512; ka = k0 - 768; }
    } else { Asrc = a.A; lda = a.lda; ka = k0; }
    const float* Wsrc; int ldw, kw;
    if (a.mode == 2) {
        if (k0 < 768) { Wsrc = a.W;  ldw = 768; kw = k0; }
        else          { Wsrc = a.W2; ldw = 512; kw = k0 - 768; }
    } else { Wsrc = a.W; ldw = a.ldw; kw = k0; }
#pragma unroll
    for (int i = 0; i < 4; i++) {
        int idx = tid + i * 256;
        int r = idx >> 3, c = idx & 7;
        cpasync16(base + (uint32_t)(r * PADK + c * 4) * 4,
                  Asrc + (size_t)(bm + r) * lda + ka + c * 4);
    }
#pragma unroll
    for (int i = 0; i < 4; i++) {
        int idx = tid + i * 256;
        int r = idx >> 3, c = idx & 7;
        cpasync16(base + TILE_FLOATS * 4 + (uint32_t)(r * PADK + c * 4) * 4,
                  Wsrc + (size_t)(bn + r) * ldw + kw + c * 4);
    }
}

__global__ void __launch_bounds__(256, 2) mma_gemm_kernel(const GArgs a) {
    extern __shared__ float sm[];
    const uint32_t smb = smem_u32(sm);

    const int tid = threadIdx.x;
    const int wid = tid >> 5, lane = tid & 31;
    const int wm = wid & 3, wn = wid >> 2;
    const int gid = lane >> 2, tg = lane & 3;
    const int bm = blockIdx.y * 128;
    const int bn = blockIdx.x * 128;
    const int acol = 8 * tg;

    float acc[2][8][4];
#pragma unroll
    for (int mt = 0; mt < 2; mt++)
#pragma unroll
        for (int nt = 0; nt < 8; nt++)
#pragma unroll
            for (int e = 0; e < 4; e++) acc[mt][nt][e] = 0.0f;

    const int KT = a.K >> 5;
    load_stage(smb, a, bm, bn, 0, tid, 0);
    CP_COMMIT();

    for (int kt = 0; kt < KT; kt++) {
        const int cur = kt & 1;
        if (kt + 1 < KT) {
            load_stage(smb, a, bm, bn, (kt + 1) * 32, tid, cur ^ 1);
            CP_COMMIT();
            CP_WAIT1();
        } else {
            CP_WAIT0();
        }
        __syncthreads();

        const float* As = sm + cur * BUF_FLOATS;
        const float* Bs = As + TILE_FLOATS;
#pragma unroll
        for (int half = 0; half < 2; half++) {
            // float4 covers stored positions acol+4*half+{0..3} =
            // MMA slots (g=2*half,h=0),(g=2*half,h=1),(g=2*half+1,h=0),(g=2*half+1,h=1)
            float4 fa[2][2];
#pragma unroll
            for (int mt = 0; mt < 2; mt++) {
                int r0 = wm * 32 + mt * 16 + gid;
                fa[mt][0] = *(const float4*)&As[r0 * PADK + acol + 4 * half];
                fa[mt][1] = *(const float4*)&As[(r0 + 8) * PADK + acol + 4 * half];
            }
            float4 fb[8];
#pragma unroll
            for (int nt = 0; nt < 8; nt++) {
                int n0 = wn * 64 + nt * 8 + gid;
                fb[nt] = *(const float4*)&Bs[n0 * PADK + acol + 4 * half];
            }
#pragma unroll
            for (int g = 0; g < 2; g++) {
#pragma unroll
                for (int mt = 0; mt < 2; mt++) {
                    uint32_t A4[4];
                    A4[0] = __float_as_uint(g ? fa[mt][0].z : fa[mt][0].x);
                    A4[1] = __float_as_uint(g ? fa[mt][1].z : fa[mt][1].x);
                    A4[2] = __float_as_uint(g ? fa[mt][0].w : fa[mt][0].y);
                    A4[3] = __float_as_uint(g ? fa[mt][1].w : fa[mt][1].y);
#pragma unroll
                    for (int nt = 0; nt < 8; nt++) {
                        uint32_t B2[2];
                        B2[0] = __float_as_uint(g ? fb[nt].z : fb[nt].x);
                        B2[1] = __float_as_uint(g ? fb[nt].w : fb[nt].y);
                        mma8(acc[mt][nt], A4, B2);
                    }
                }
            }
        }
        __syncthreads();
    }

    if (a.mode == 0) {
#pragma unroll
        for (int mt = 0; mt < 2; mt++) {
            const size_t r0 = (size_t)bm + wm * 32 + mt * 16 + gid;
            const size_t r1 = r0 + 8;
#pragma unroll
            for (int nt = 0; nt < 8; nt++) {
                const int col = bn + wn * 64 + nt * 8 + tg * 2;
                float2 v0 = make_float2(acc[mt][nt][0], acc[mt][nt][1]);
                float2 v1 = make_float2(acc[mt][nt][2], acc[mt][nt][3]);
                if (a.bias) {
                    float2 b2 = *(const float2*)(a.bias + col);
                    v0.x += b2.x; v0.y += b2.y; v1.x += b2.x; v1.y += b2.y;
                }
                if (a.Cin) {
                    float2 c0 = *(const float2*)(a.Cin + r0 * a.ldc + col);
                    float2 c1 = *(const float2*)(a.Cin + r1 * a.ldc + col);
                    v0.x += c0.x; v0.y += c0.y; v1.x += c1.x; v1.y += c1.y;
                }
                if (a.trunc_out) {
                    v0.x = tff(v0.x); v0.y = tff(v0.y);
                    v1.x = tff(v1.x); v1.y = tff(v1.y);
                }
                *(float2*)(a.C + r0 * a.ldc + col) = v0;
                *(float2*)(a.C + r1 * a.ldc + col) = v1;
            }
        }
    } else {
        // fused LSTM epilogue (gates permuted 4j+t in N)
        float* gsm = sm;
#pragma unroll
        for (int mt = 0; mt < 2; mt++) {
            const int lr0 = wm * 32 + mt * 16 + gid;
            const int lr1 = lr0 + 8;
#pragma unroll
            for (int nt = 0; nt < 8; nt++) {
                const int lc = wn * 64 + nt * 8 + tg * 2;
                float2 v0 = make_float2(acc[mt][nt][0], acc[mt][nt][1]);
                float2 v1 = make_float2(acc[mt][nt][2], acc[mt][nt][3]);
                if (a.bias) {
                    float2 b2 = *(const float2*)(a.bias + bn + lc);
                    v0.x += b2.x; v0.y += b2.y; v1.x += b2.x; v1.y += b2.y;
                }
                if (a.Cin) {
                    float2 c0 = *(const float2*)(a.Cin + (size_t)(bm + lr0) * a.ldc + bn + lc);
                    float2 c1 = *(const float2*)(a.Cin + (size_t)(bm + lr1) * a.ldc + bn + lc);
                    v0.x += c0.x; v0.y += c0.y; v1.x += c1.x; v1.y += c1.y;
                }
                *(float2*)&gsm[lr0 * 132 + lc] = v0;
                *(float2*)&gsm[lr1 * 132 + lc] = v1;
            }
        }
        __syncthreads();
        const int jb = bn >> 2;   // 32 units per CTA, block-aligned
#pragma unroll
        for (int it = 0; it < 16; it++) {
            int idx = tid + it * 256;
            int row = idx >> 5, u = idx & 31;
            float4 gt = *(float4*)&gsm[row * 132 + 4 * u];
            float ii = sigf(gt.x), ff = sigf(gt.y);
            float gg = tanh_fast(gt.z), oo = sigf(gt.w);
            size_t e = (size_t)(bm + row) * HH + jb + u;           // true j index
            float c_new = ff * a.c_in[e] + ii * gg;
            float h_new = oo * tanh_fast(c_new);
            a.c_out[e] = c_new;
            if (a.h_full) a.h_full[e] = h_new;
            if (a.h_tf) {  // store h in permuted-K order for the next GEMM
                size_t ep = (size_t)(bm + row) * HH + jb + KPERM(u);
                a.h_tf[ep] = tff(h_new);
            }
        }
    }
}

static void launch_g(const GArgs& a, int M, int N) {
    static int attr_set = 0;
    if (!attr_set) {
        cudaFuncSetAttribute(mma_gemm_kernel,
                             cudaFuncAttributeMaxDynamicSharedMemorySize, SMEM_DYN);
        attr_set = 1;
    }
    dim3 grid(N / 128, M / 128);
    mma_gemm_kernel<<<grid, 256, SMEM_DYN>>>(a);
}

// ------------------------------ prep kernels --------------------------------
__device__ __forceinline__ int porig(int p) { return ((p & 3) << 9) | (p >> 2); }

#define PR0 ((size_t)1114112)            // wihp  2048*544
#define PR1 (PR0 + 1048576)              // whhp
#define PR2 (PR1 + 1572864)              // wihop
#define PR3 (PR2 + 1048576)              // whhop
#define PR4 (PR3 + 524288)               // xtf
#define PR5 (PR4 + 1048576)              // hltf
#define PR6 (PR5 + 131072)               // wqtf
#define PR7 (PR6 + 131072)               // wkT
#define PR8 (PR7 + 65536)                // wvtf
#define PR9 (PR8 + 2048)                 // g_bias
#define PRA (PR9 + 2048)                 // g_biaso

__global__ void prep_kernel(const float* __restrict__ Wih, const float* __restrict__ Whh,
                            const float* __restrict__ bih, const float* __restrict__ bhh,
                            const float* __restrict__ Wiho, const float* __restrict__ Whho,
                            const float* __restrict__ biho,
                            const float* __restrict__ x, const float* __restrict__ hl,
                            const float* __restrict__ Wq, const float* __restrict__ Wk,
                            const float* __restrict__ Wv) {
    size_t e = (size_t)blockIdx.x * blockDim.x + threadIdx.x;
    if (e < PR0) {
        int p = (int)(e / FEATP), kp = (int)(e % FEATP);
        size_t f = PIF((size_t)kp);
        g_wihp[e] = (f < FEAT) ? tff(Wih[(size_t)porig(p) * FEAT + f]) : 0.0f;
    } else if (e < PR1) {
        size_t i = e - PR0; int p = (int)(i >> 9), kp = (int)(i & 511);
        g_whhp[i] = tff(Whh[(size_t)porig(p) * 512 + PIF((size_t)kp)]);
    } else if (e < PR2) {
        size_t i = e - PR1; int p = (int)(i / 768), kp = (int)(i % 768);
        g_wihop[i] = tff(Wiho[(size_t)porig(p) * 768 + PIF((size_t)kp)]);
    } else if (e < PR3) {
        size_t i = e - PR2; int p = (int)(i >> 9), kp = (int)(i & 511);
        g_whhop[i] = tff(Whho[(size_t)porig(p) * 512 + PIF((size_t)kp)]);
    } else if (e < PR4) {
        size_t i = e - PR3; g_xtf[i] = tff(x[PIF(i)]);
    } else if (e < PR5) {
        size_t i = e - PR4; g_hltf[i] = tff(hl[PIF(i)]);
    } else if (e < PR6) {
        size_t i = e - PR5; size_t r = i >> 8, kp = i & 255;
        g_wqtf[i] = tff(Wq[PIF(r) * 256 + PIF(kp)]);   // N rows AND K cols permuted
    } else if (e < PR7) {
        size_t i = e - PR6; size_t d = i >> 9, p = i & 511;
        g_wkT[i] = tff(Wk[PIF(p) * 256 + d]);
    } else if (e < PR8) {
        size_t i = e - PR7;
        g_wvtf[i] = tff(Wv[(i & ~(size_t)255) + PIF(i & 255)]);
    } else if (e < PR9) {
        int p = (int)(e - PR8); int o = porig(p);
        g_bias[p] = bih[o] + bhh[o];
    } else if (e < PRA) {
        int p = (int)(e - PR9);
        g_biaso[p] = biho[porig(p)];
    }
}

__global__ void zero_hc_kernel() {
    int e = blockIdx.x * blockDim.x + threadIdx.x;
    if (e < BB * HH) { g_htf0[e] = 0.0f; g_c[e] = 0.0f; }
}

__global__ void detect_filled_kernel(const unsigned int* __restrict__ w) {
    __shared__ int flags[3];
    if (threadIdx.x < 3) flags[threadIdx.x] = 0;
    __syncthreads();
    for (int i = threadIdx.x; i < (BB * NSLOT) / 4; i += blockDim.x) {
        unsigned v = w[i];
        if (v == 0x3F800000u)      atomicOr(&flags[0], 1);
        else if (v == 0x3F803F80u) atomicOr(&flags[1], 1);
        else if (v > 1u)           atomicOr(&flags[2], 1);
    }
    __syncthreads();
    if (threadIdx.x == 0) {
        int m;
        if (flags[1])      m = 3;
        else if (flags[0]) m = 0;
        else if (flags[2]) m = 2;
        else               m = 1;
        g_fmode = m;
    }
}

__global__ void select_idx_kernel(const float* __restrict__ slots,
                                  const void* __restrict__ filled) {
    const int b = blockIdx.x;
    const int t = threadIdx.x;
    __shared__ float kq_s[DD];
    __shared__ float sims[NSLOT];
    __shared__ int   emp[NSLOT];
    for (int d = t; d < DD; d += NSLOT) kq_s[d] = g_kq[b * DD + d];
    __syncthreads();
    const float* sp = slots + ((size_t)b * NSLOT + t) * DD;
    float s = 0.0f;
    for (int d = 0; d < DD; d++) s = fmaf(sp[d], kq_s[d], s);
    sims[t] = s;
    emp[t]  = !read_filled(filled, (size_t)b * NSLOT + t, g_fmode);
    __syncthreads();
    if (t == 0) {
        int idx = -1;
        for (int n = 0; n < NSLOT; n++) if (emp[n]) { idx = n; break; }
        if (idx < 0) {
            float best = sims[0]; idx = 0;
            for (int n = 1; n < NSLOT; n++) if (sims[n] > best) { best = sims[n]; idx = n; }
        }
        g_idx[b] = idx;
    }
}

__global__ void update_write_kernel(const float* __restrict__ slots,
                                    const float* __restrict__ cum,
                                    const float* __restrict__ delta,
                                    const void* __restrict__ filled,
                                    const float* __restrict__ x,
                                    float* __restrict__ out) {
    size_t e = (size_t)blockIdx.x * blockDim.x + threadIdx.x;
    if (e >= (size_t)BB * NSLOT * DD) return;
    int d = (int)(e % DD);
    size_t bn = e / DD;
    int n = (int)(bn % NSLOT);
    int b = (int)(bn / NSLOT);
    int idx = g_idx[b];

    float xv = x[b * DD + d];
    float sl = slots[e];
    float cf = cum[e] + xv;
    if (n == idx) { sl = g_v[b * DD + d]; cf = xv; }

    out[OFF_SLOTS + e] = sl;
    out[OFF_CUM + e]   = cf;

    size_t mbase = ((size_t)n * BB + b) * FEATP;
    int dp = (d & ~31) | KPERM(d & 31);          // permuted-K feature position
    g_mem[mbase + dp]       = tff(sl);
    g_mem[mbase + 256 + dp] = tff(cf);
    if (d < FEATP - FEAT) g_mem[mbase + FEAT + d] = 0.0f;   // stored pads 513..543
    if (d == 0) {
        float dt = (n == idx) ? 0.0f : delta[bn] + 1.0f;
        out[OFF_DELTA + bn] = dt;
        g_mem[mbase + 512] = tff(dt);            // KPERM(0)=0
        int fl = (n == idx) ? 1 : read_filled(filled, bn, g_fmode);
        out[OFF_FILLED + bn] = fl ? 1.0f : 0.0f;
    }
}

// --------------------------------- launch -----------------------------------
extern "C" void kernel_launch(void* const* d_in, const int* in_sizes, int n_in,
                              void* d_out, int out_size) {
    const float* x_t      = (const float*)d_in[0];
    const float* h_lstm   = (const float*)d_in[1];
    const float* c_lstm   = (const float*)d_in[2];
    const float* slots    = (const float*)d_in[4];
    const float* cum      = (const float*)d_in[5];
    const float* delta    = (const float*)d_in[6];
    const void*  filled   = (const void*)d_in[7];
    const float* Wq       = (const float*)d_in[8];
    const float* Wk       = (const float*)d_in[9];
    const float* Wv       = (const float*)d_in[10];
    const float* bv       = (const float*)d_in[11];
    const float* lstm_Wih = (const float*)d_in[12];
    const float* lstm_Whh = (const float*)d_in[13];
    const float* lstm_bih = (const float*)d_in[14];
    const float* lstm_bhh = (const float*)d_in[15];
    const float* W_ih     = (const float*)d_in[16];
    const float* b_ih     = (const float*)d_in[17];
    const float* W_hh     = (const float*)d_in[18];
    float* out = (float*)d_out;

    float *p_q, *p_kq, *p_v, *p_mem, *p_xg, *p_c, *p_bias, *p_biaso;
    float *p_wihp, *p_whhp, *p_wihop, *p_whhop, *p_xtf, *p_hltf, *p_wqtf, *p_wkT, *p_wvtf;
    float *p_h0, *p_h1;
    cudaGetSymbolAddress((void**)&p_q, g_q);
    cudaGetSymbolAddress((void**)&p_kq, g_kq);
    cudaGetSymbolAddress((void**)&p_v, g_v);
    cudaGetSymbolAddress((void**)&p_mem, g_mem);
    cudaGetSymbolAddress((void**)&p_xg, g_xg);
    cudaGetSymbolAddress((void**)&p_c, g_c);
    cudaGetSymbolAddress((void**)&p_bias, g_bias);
    cudaGetSymbolAddress((void**)&p_biaso, g_biaso);
    cudaGetSymbolAddress((void**)&p_wihp, g_wihp);
    cudaGetSymbolAddress((void**)&p_whhp, g_whhp);
    cudaGetSymbolAddress((void**)&p_wihop, g_wihop);
    cudaGetSymbolAddress((void**)&p_whhop, g_whhop);
    cudaGetSymbolAddress((void**)&p_xtf, g_xtf);
    cudaGetSymbolAddress((void**)&p_hltf, g_hltf);
    cudaGetSymbolAddress((void**)&p_wqtf, g_wqtf);
    cudaGetSymbolAddress((void**)&p_wkT, g_wkT);
    cudaGetSymbolAddress((void**)&p_wvtf, g_wvtf);
    cudaGetSymbolAddress((void**)&p_h0, g_htf0);
    cudaGetSymbolAddress((void**)&p_h1, g_htf1);

    detect_filled_kernel<<<1, 256>>>((const unsigned int*)filled);
    zero_hc_kernel<<<(BB * HH + 255) / 256, 256>>>();
    prep_kernel<<<(unsigned)((PRA + 255) / 256), 256>>>(
        lstm_Wih, lstm_Whh, lstm_bih, lstm_bhh,
        W_ih, W_hh, b_ih, x_t, h_lstm, Wq, Wk, Wv);

    GArgs a;
    // q = x @ Wq.T  (cols in storage order via Wq row perm; trunc for next GEMM)
    a = {}; a.mode = 0; a.K = 256; a.lda = 256; a.ldw = 256; a.ldc = 512;
    a.trunc_out = 1; a.A = p_xtf; a.W = p_wqtf; a.C = p_q;
    launch_g(a, BB, HH);
    // kq = q @ Wk
    a = {}; a.mode = 0; a.K = 512; a.lda = 512; a.ldw = 512; a.ldc = 256;
    a.A = p_q; a.W = p_wkT; a.C = p_kq;
    launch_g(a, BB, DD);
    // v = x @ Wv.T + bv
    a = {}; a.mode = 0; a.K = 256; a.lda = 256; a.ldw = 256; a.ldc = 256;
    a.A = p_xtf; a.W = p_wvtf; a.bias = bv; a.C = p_v;
    launch_g(a, BB, DD);

    select_idx_kernel<<<BB, NSLOT>>>(slots, filled);
    {
        size_t tot = (size_t)BB * NSLOT * DD;
        update_write_kernel<<<(unsigned)((tot + 255) / 256), 256>>>(
            slots, cum, delta, filled, x_t, out);
    }

    // xg = mem_seq @ WihP.T + biasP
    a = {}; a.mode = 0; a.K = FEATP; a.lda = FEATP; a.ldw = FEATP; a.ldc = G4;
    a.A = p_mem; a.W = p_wihp; a.bias = p_bias; a.C = p_xg;
    launch_g(a, NSLOT * BB, G4);

    // slot-LSTM recurrence (fused pointwise, h ping-pong in permuted-K order)
    for (int n = 0; n < NSLOT; n++) {
        a = {}; a.mode = 1; a.K = HH; a.lda = HH; a.ldw = HH; a.ldc = G4;
        a.A = (n & 1) ? p_h1 : p_h0;
        a.W = p_whhp;
        a.Cin = p_xg + (size_t)n * BB * G4;
        a.c_in = p_c; a.c_out = p_c;
        a.h_tf = (n & 1) ? p_h0 : p_h1;
        a.h_full = (n == NSLOT - 1) ? (out + OFF_HMEM) : nullptr;
        launch_g(a, BB, G4);
    }

    // outer LSTM: segmented K = [x(256) | h_mem(512) | h_lstm(512)]
    a = {}; a.mode = 2; a.K = 1280; a.ldc = G4;
    a.A = p_xtf; a.A2 = p_h0; a.A3 = p_hltf;
    a.W = p_wihop; a.W2 = p_whhop; a.bias = p_biaso;
    a.c_in = c_lstm; a.c_out = out + OFF_C; a.h_full = out + OFF_H;
    launch_g(a, BB, G4);
}

// round 9
// speedup vs baseline: 1.0989x; 1.0989x over previous
#include <cuda_runtime.h>
#include <math.h>
#include <stdint.h>

#define BB    2048
#define DD    256
#define HH    512
#define NSLOT 64
#define FEAT  513
#define FEATP 544
#define G4    2048
#define KSTEP 1056          // 512 (h) + 544 (mem)
#define KOUT  1280          // 256 (x) + 512 (h_mem) + 512 (h_lstm)

#define OFF_H      ((size_t)0)
#define OFF_C      ((size_t)1048576)
#define OFF_HMEM   ((size_t)2097152)
#define OFF_SLOTS  ((size_t)3145728)
#define OFF_CUM    ((size_t)36700160)
#define OFF_DELTA  ((size_t)70254592)
#define OFF_FILLED ((size_t)70385664)

// ------------------------------- scratch ------------------------------------
__device__ float g_q[BB * HH];
__device__ float g_kq[BB * DD];
__device__ float g_v[BB * DD];
__device__ int   g_idx[BB];
__device__ float g_bias[G4];                     // permuted bih+bhh
__device__ float g_biaso[G4];                    // permuted outer b_ih
__device__ float g_wstep[(size_t)G4 * KSTEP];    // [Whh | Wih] permuted rows, trunc
__device__ float g_wout[(size_t)G4 * KOUT];      // [W_ih | W_hh] permuted rows, trunc
__device__ float g_xtf[BB * DD];
__device__ float g_hltf[BB * HH];
__device__ float g_wqtf[HH * DD];
__device__ float g_wkT[DD * HH];
__device__ float g_wvtf[DD * DD];
__device__ float g_mem[(size_t)NSLOT * BB * FEATP];  // trunc mem_seq [n][b][f]
__device__ float g_h0[BB * HH];                  // trunc h ping
__device__ float g_h1[BB * HH];                  // trunc h pong
__device__ float g_c[BB * HH];                   // slot-LSTM cell (fp32)
__device__ int   g_fmode;

__device__ __forceinline__ uint32_t f2tf(float x) {
    uint32_t r;
    asm("cvt.rna.tf32.f32 %0, %1;" : "=r"(r) : "f"(x));
    return r;
}
__device__ __forceinline__ float tff(float x) { return __uint_as_float(f2tf(x)); }

__device__ __forceinline__ float sigf(float x) { return 1.0f / (1.0f + __expf(-x)); }
__device__ __forceinline__ float tanh_fast(float x) {
    float t = __expf(-2.0f * fabsf(x));
    float r = (1.0f - t) / (1.0f + t);
    return copysignf(r, x);
}

__device__ __forceinline__ int read_filled(const void* p, size_t i, int m) {
    if (m == 0) return ((const float*)p)[i] != 0.0f;
    if (m == 1) return ((const int*)p)[i] != 0;
    if (m == 2) return ((const unsigned char*)p)[i] != 0;
    return ((const unsigned short*)p)[i] != 0;
}

// ----------------------------- PTX helpers ----------------------------------
__device__ __forceinline__ uint32_t smem_u32(const void* p) {
    uint32_t a;
    asm("{ .reg .u64 t; cvta.to.shared.u64 t, %1; cvt.u32.u64 %0, t; }" : "=r"(a) : "l"(p));
    return a;
}
__device__ __forceinline__ void cpasync16(uint32_t dst, const void* src) {
    asm volatile("cp.async.cg.shared.global [%0], [%1], 16;\n" :: "r"(dst), "l"(src));
}
#define CP_COMMIT() asm volatile("cp.async.commit_group;\n" ::: "memory")
#define CP_WAIT1()  asm volatile("cp.async.wait_group 1;\n" ::: "memory")

__device__ __forceinline__ void mma8(float* c, const uint32_t* A, const uint32_t* B) {
    asm volatile(
        "mma.sync.aligned.m16n8k8.row.col.f32.tf32.tf32.f32 "
        "{%0,%1,%2,%3}, {%4,%5,%6,%7}, {%8,%9}, {%0,%1,%2,%3};"
        : "+f"(c[0]), "+f"(c[1]), "+f"(c[2]), "+f"(c[3])
        : "r"(A[0]), "r"(A[1]), "r"(A[2]), "r"(A[3]), "r"(B[0]), "r"(B[1]));
}

// ------------------------- tf32 warp-MMA GEMM -------------------------------
// All operands pre-truncated to tf32. C = A[M,K] @ W[N,K]^T (+bias)(+Cin).
// mode 0: plain store; mode 1: step LSTM (A = [h | mem_n]); mode 2: outer LSTM.
#define PADK 36
#define TILE_FLOATS 4608
#define BUF_FLOATS  9216
#define SMEM_DYN    (3 * BUF_FLOATS * 4)     // 110592 B, 3 stages

struct GArgs {
    int mode, K, lda, ldw, ldc, trunc_out;
    const float *A, *A2, *A3, *W, *bias, *Cin, *c_in;
    float *C, *c_out, *h_full, *h_tf;
};

__device__ __forceinline__ void load_stage(uint32_t smb, const GArgs& a,
                                           int bm, int bn, int k0, int tid, int buf) {
    const uint32_t base = smb + (uint32_t)buf * BUF_FLOATS * 4;
    const float* Asrc; int lda, ka;
    if (a.mode == 1) {
        if (k0 < 512) { Asrc = a.A;  lda = 512;   ka = k0; }
        else          { Asrc = a.A2; lda = FEATP; ka = k0 - 512; }
    } else if (a.mode == 2) {
        if (k0 < 256)      { Asrc = a.A;  lda = 256; ka = k0; }
        else if (k0 < 768) { Asrc = a.A2; lda = 512; ka = k0 - 256; }
        else               { Asrc = a.A3; lda = 512; ka = k0 - 768; }
    } else { Asrc = a.A; lda = a.lda; ka = k0; }
#pragma unroll
    for (int i = 0; i < 4; i++) {
        int idx = tid + i * 256;
        int r = idx >> 3, c = idx & 7;
        cpasync16(base + (uint32_t)(r * PADK + c * 4) * 4,
                  Asrc + (size_t)(bm + r) * lda + ka + c * 4);
    }
#pragma unroll
    for (int i = 0; i < 4; i++) {
        int idx = tid + i * 256;
        int r = idx >> 3, c = idx & 7;
        cpasync16(base + TILE_FLOATS * 4 + (uint32_t)(r * PADK + c * 4) * 4,
                  a.W + (size_t)(bn + r) * a.ldw + k0 + c * 4);
    }
}

__global__ void __launch_bounds__(256, 2) mma_gemm_kernel(const GArgs a) {
    extern __shared__ float sm[];
    const uint32_t smb = smem_u32(sm);

    const int tid = threadIdx.x;
    const int wid = tid >> 5, lane = tid & 31;
    const int wm = wid & 3, wn = wid >> 2;
    const int gid = lane >> 2, tg = lane & 3;
    const int bm = blockIdx.y * 128;
    const int bn = blockIdx.x * 128;

    float acc[2][8][4];
#pragma unroll
    for (int mt = 0; mt < 2; mt++)
#pragma unroll
        for (int nt = 0; nt < 8; nt++)
#pragma unroll
            for (int e = 0; e < 4; e++) acc[mt][nt][e] = 0.0f;

    const int KT = a.K >> 5;
    load_stage(smb, a, bm, bn, 0, tid, 0);
    CP_COMMIT();
    if (KT > 1) load_stage(smb, a, bm, bn, 32, tid, 1);
    CP_COMMIT();

    for (int kt = 0; kt < KT; kt++) {
        CP_WAIT1();
        __syncthreads();
        if (kt + 2 < KT)
            load_stage(smb, a, bm, bn, (kt + 2) * 32, tid, (kt + 2) % 3);
        CP_COMMIT();

        const float* As = sm + (kt % 3) * BUF_FLOATS;
        const float* Bs = As + TILE_FLOATS;
#pragma unroll
        for (int k8 = 0; k8 < 4; k8++) {
            const int kb = k8 * 8;
            uint32_t af[2][4];
#pragma unroll
            for (int mt = 0; mt < 2; mt++) {
                int r0 = wm * 32 + mt * 16 + gid;
                af[mt][0] = __float_as_uint(As[r0 * PADK + kb + tg]);
                af[mt][1] = __float_as_uint(As[(r0 + 8) * PADK + kb + tg]);
                af[mt][2] = __float_as_uint(As[r0 * PADK + kb + tg + 4]);
                af[mt][3] = __float_as_uint(As[(r0 + 8) * PADK + kb + tg + 4]);
            }
            uint32_t bf[8][2];
#pragma unroll
            for (int nt = 0; nt < 8; nt++) {
                int n0 = wn * 64 + nt * 8 + gid;
                bf[nt][0] = __float_as_uint(Bs[n0 * PADK + kb + tg]);
                bf[nt][1] = __float_as_uint(Bs[n0 * PADK + kb + tg + 4]);
            }
#pragma unroll
            for (int mt = 0; mt < 2; mt++)
#pragma unroll
                for (int nt = 0; nt < 8; nt++)
                    mma8(acc[mt][nt], af[mt], bf[nt]);
        }
        __syncthreads();
    }

    if (a.mode == 0) {
#pragma unroll
        for (int mt = 0; mt < 2; mt++) {
            const size_t r0 = (size_t)bm + wm * 32 + mt * 16 + gid;
            const size_t r1 = r0 + 8;
#pragma unroll
            for (int nt = 0; nt < 8; nt++) {
                const int col = bn + wn * 64 + nt * 8 + tg * 2;
                float2 v0 = make_float2(acc[mt][nt][0], acc[mt][nt][1]);
                float2 v1 = make_float2(acc[mt][nt][2], acc[mt][nt][3]);
                if (a.bias) {
                    float2 b2 = *(const float2*)(a.bias + col);
                    v0.x += b2.x; v0.y += b2.y; v1.x += b2.x; v1.y += b2.y;
                }
                if (a.Cin) {
                    float2 c0 = *(const float2*)(a.Cin + r0 * a.ldc + col);
                    float2 c1 = *(const float2*)(a.Cin + r1 * a.ldc + col);
                    v0.x += c0.x; v0.y += c0.y; v1.x += c1.x; v1.y += c1.y;
                }
                if (a.trunc_out) {
                    v0.x = tff(v0.x); v0.y = tff(v0.y);
                    v1.x = tff(v1.x); v1.y = tff(v1.y);
                }
                *(float2*)(a.C + r0 * a.ldc + col) = v0;
                *(float2*)(a.C + r1 * a.ldc + col) = v1;
            }
        }
    } else {
        // fused LSTM epilogue (gate columns permuted 4j+t)
        float* gsm = sm;
#pragma unroll
        for (int mt = 0; mt < 2; mt++) {
            const int lr0 = wm * 32 + mt * 16 + gid;
            const int lr1 = lr0 + 8;
#pragma unroll
            for (int nt = 0; nt < 8; nt++) {
                const int lc = wn * 64 + nt * 8 + tg * 2;
                float2 v0 = make_float2(acc[mt][nt][0], acc[mt][nt][1]);
                float2 v1 = make_float2(acc[mt][nt][2], acc[mt][nt][3]);
                if (a.bias) {
                    float2 b2 = *(const float2*)(a.bias + bn + lc);
                    v0.x += b2.x; v0.y += b2.y; v1.x += b2.x; v1.y += b2.y;
                }
                *(float2*)&gsm[lr0 * 132 + lc] = v0;
                *(float2*)&gsm[lr1 * 132 + lc] = v1;
            }
        }
        __syncthreads();
        const int jb = bn >> 2;
#pragma unroll
        for (int it = 0; it < 16; it++) {
            int idx = tid + it * 256;
            int row = idx >> 5, u = idx & 31;
            float4 gt = *(float4*)&gsm[row * 132 + 4 * u];
            float ii = sigf(gt.x), ff = sigf(gt.y);
            float gg = tanh_fast(gt.z), oo = sigf(gt.w);
            size_t e = (size_t)(bm + row) * HH + jb + u;
            float c_new = ff * a.c_in[e] + ii * gg;
            float h_new = oo * tanh_fast(c_new);
            a.c_out[e] = c_new;
            if (a.h_full) a.h_full[e] = h_new;
            if (a.h_tf)   a.h_tf[e] = tff(h_new);
        }
    }
}

static void launch_g(const GArgs& a, int M, int N) {
    static int attr_set = 0;
    if (!attr_set) {
        cudaFuncSetAttribute(mma_gemm_kernel,
                             cudaFuncAttributeMaxDynamicSharedMemorySize, SMEM_DYN);
        attr_set = 1;
    }
    dim3 grid(N / 128, M / 128);
    mma_gemm_kernel<<<grid, 256, SMEM_DYN>>>(a);
}

// ------------------------------ prep kernels --------------------------------
__device__ __forceinline__ int porig(int p) { return ((p & 3) << 9) | (p >> 2); }

#define Q0 ((size_t)G4 * KSTEP)          // 2162688  wstep
#define Q1 (Q0 + (size_t)G4 * KOUT)      // +2621440 wout
#define Q2 (Q1 + (size_t)BB * DD)        // xtf
#define Q3 (Q2 + (size_t)BB * HH)        // hltf
#define Q4 (Q3 + (size_t)HH * DD)        // wqtf
#define Q5 (Q4 + (size_t)DD * HH)        // wkT
#define Q6 (Q5 + (size_t)DD * DD)        // wvtf
#define Q7 (Q6 + G4)                     // bias
#define Q8 (Q7 + G4)                     // biaso

__global__ void prep_kernel(const float* __restrict__ Wih, const float* __restrict__ Whh,
                            const float* __restrict__ bih, const float* __restrict__ bhh,
                            const float* __restrict__ Wiho, const float* __restrict__ Whho,
                            const float* __restrict__ biho,
                            const float* __restrict__ x, const float* __restrict__ hl,
                            const float* __restrict__ Wq, const float* __restrict__ Wk,
                            const float* __restrict__ Wv) {
    size_t e = (size_t)blockIdx.x * blockDim.x + threadIdx.x;
    if (e < Q0) {
        int p = (int)(e / KSTEP), k = (int)(e % KSTEP);
        if (k < 512) g_wstep[e] = tff(Whh[(size_t)porig(p) * 512 + k]);
        else {
            int f = k - 512;
            g_wstep[e] = (f < FEAT) ? tff(Wih[(size_t)porig(p) * FEAT + f]) : 0.0f;
        }
    } else if (e < Q1) {
        size_t i = e - Q0; int p = (int)(i / KOUT), k = (int)(i % KOUT);
        g_wout[i] = (k < 768) ? tff(Wiho[(size_t)porig(p) * 768 + k])
                              : tff(Whho[(size_t)porig(p) * 512 + (k - 768)]);
    } else if (e < Q2) {
        size_t i = e - Q1; g_xtf[i] = tff(x[i]);
    } else if (e < Q3) {
        size_t i = e - Q2; g_hltf[i] = tff(hl[i]);
    } else if (e < Q4) {
        size_t i = e - Q3; g_wqtf[i] = tff(Wq[i]);
    } else if (e < Q5) {
        size_t i = e - Q4; size_t d = i >> 9, h = i & 511;
        g_wkT[i] = tff(Wk[h * 256 + d]);
    } else if (e < Q6) {
        size_t i = e - Q5; g_wvtf[i] = tff(Wv[i]);
    } else if (e < Q7) {
        int p = (int)(e - Q6); int o = porig(p);
        g_bias[p] = bih[o] + bhh[o];
    } else if (e < Q8) {
        int p = (int)(e - Q7);
        g_biaso[p] = biho[porig(p)];
    }
}

__global__ void zero_hc_kernel() {
    int e = blockIdx.x * blockDim.x + threadIdx.x;
    if (e < BB * HH) { g_h0[e] = 0.0f; g_c[e] = 0.0f; }
}

__global__ void detect_filled_kernel(const unsigned int* __restrict__ w) {
    __shared__ int flags[3];
    if (threadIdx.x < 3) flags[threadIdx.x] = 0;
    __syncthreads();
    for (int i = threadIdx.x; i < (BB * NSLOT) / 4; i += blockDim.x) {
        unsigned v = w[i];
        if (v == 0x3F800000u)      atomicOr(&flags[0], 1);
        else if (v == 0x3F803F80u) atomicOr(&flags[1], 1);
        else if (v > 1u)           atomicOr(&flags[2], 1);
    }
    __syncthreads();
    if (threadIdx.x == 0) {
        int m;
        if (flags[1])      m = 3;
        else if (flags[0]) m = 0;
        else if (flags[2]) m = 2;
        else               m = 1;
        g_fmode = m;
    }
}

__global__ void select_idx_kernel(const float* __restrict__ slots,
                                  const void* __restrict__ filled) {
    const int b = blockIdx.x;
    const int t = threadIdx.x;
    __shared__ float kq_s[DD];
    __shared__ float sims[NSLOT];
    __shared__ int   emp[NSLOT];
    for (int d = t; d < DD; d += NSLOT) kq_s[d] = g_kq[b * DD + d];
    __syncthreads();
    const float* sp = slots + ((size_t)b * NSLOT + t) * DD;
    float s = 0.0f;
    for (int d = 0; d < DD; d++) s = fmaf(sp[d], kq_s[d], s);
    sims[t] = s;
    emp[t]  = !read_filled(filled, (size_t)b * NSLOT + t, g_fmode);
    __syncthreads();
    if (t == 0) {
        int idx = -1;
        for (int n = 0; n < NSLOT; n++) if (emp[n]) { idx = n; break; }
        if (idx < 0) {
            float best = sims[0]; idx = 0;
            for (int n = 1; n < NSLOT; n++) if (sims[n] > best) { best = sims[n]; idx = n; }
        }
        g_idx[b] = idx;
    }
}

__global__ void update_write_kernel(const float* __restrict__ slots,
                                    const float* __restrict__ cum,
                                    const float* __restrict__ delta,
                                    const void* __restrict__ filled,
                                    const float* __restrict__ x,
                                    float* __restrict__ out) {
    size_t e = (size_t)blockIdx.x * blockDim.x + threadIdx.x;
    if (e >= (size_t)BB * NSLOT * DD) return;
    int d = (int)(e % DD);
    size_t bn = e / DD;
    int n = (int)(bn % NSLOT);
    int b = (int)(bn / NSLOT);
    int idx = g_idx[b];

    float xv = x[b * DD + d];
    float sl = slots[e];
    float cf = cum[e] + xv;
    if (n == idx) { sl = g_v[b * DD + d]; cf = xv; }

    out[OFF_SLOTS + e] = sl;
    out[OFF_CUM + e]   = cf;

    size_t mbase = ((size_t)n * BB + b) * FEATP;
    g_mem[mbase + d]      = tff(sl);
    g_mem[mbase + DD + d] = tff(cf);
    if (d < FEATP - FEAT) g_mem[mbase + FEAT + d] = 0.0f;
    if (d == 0) {
        float dt = (n == idx) ? 0.0f : delta[bn] + 1.0f;
        out[OFF_DELTA + bn] = dt;
        g_mem[mbase + 2 * DD] = tff(dt);
        int fl = (n == idx) ? 1 : read_filled(filled, bn, g_fmode);
        out[OFF_FILLED + bn] = fl ? 1.0f : 0.0f;
    }
}

// --------------------------------- launch -----------------------------------
extern "C" void kernel_launch(void* const* d_in, const int* in_sizes, int n_in,
                              void* d_out, int out_size) {
    const float* x_t      = (const float*)d_in[0];
    const float* h_lstm   = (const float*)d_in[1];
    const float* c_lstm   = (const float*)d_in[2];
    const float* slots    = (const float*)d_in[4];
    const float* cum      = (const float*)d_in[5];
    const float* delta    = (const float*)d_in[6];
    const void*  filled   = (const void*)d_in[7];
    const float* Wq       = (const float*)d_in[8];
    const float* Wk       = (const float*)d_in[9];
    const float* Wv       = (const float*)d_in[10];
    const float* bv       = (const float*)d_in[11];
    const float* lstm_Wih = (const float*)d_in[12];
    const float* lstm_Whh = (const float*)d_in[13];
    const float* lstm_bih = (const float*)d_in[14];
    const float* lstm_bhh = (const float*)d_in[15];
    const float* W_ih     = (const float*)d_in[16];
    const float* b_ih     = (const float*)d_in[17];
    const float* W_hh     = (const float*)d_in[18];
    float* out = (float*)d_out;

    float *p_q, *p_kq, *p_v, *p_mem, *p_c, *p_bias, *p_biaso;
    float *p_wstep, *p_wout, *p_xtf, *p_hltf, *p_wqtf, *p_wkT, *p_wvtf;
    float *p_h0, *p_h1;
    cudaGetSymbolAddress((void**)&p_q, g_q);
    cudaGetSymbolAddress((void**)&p_kq, g_kq);
    cudaGetSymbolAddress((void**)&p_v, g_v);
    cudaGetSymbolAddress((void**)&p_mem, g_mem);
    cudaGetSymbolAddress((void**)&p_c, g_c);
    cudaGetSymbolAddress((void**)&p_bias, g_bias);
    cudaGetSymbolAddress((void**)&p_biaso, g_biaso);
    cudaGetSymbolAddress((void**)&p_wstep, g_wstep);
    cudaGetSymbolAddress((void**)&p_wout, g_wout);
    cudaGetSymbolAddress((void**)&p_xtf, g_xtf);
    cudaGetSymbolAddress((void**)&p_hltf, g_hltf);
    cudaGetSymbolAddress((void**)&p_wqtf, g_wqtf);
    cudaGetSymbolAddress((void**)&p_wkT, g_wkT);
    cudaGetSymbolAddress((void**)&p_wvtf, g_wvtf);
    cudaGetSymbolAddress((void**)&p_h0, g_h0);
    cudaGetSymbolAddress((void**)&p_h1, g_h1);

    detect_filled_kernel<<<1, 256>>>((const unsigned int*)filled);
    zero_hc_kernel<<<(BB * HH + 255) / 256, 256>>>();
    prep_kernel<<<(unsigned)((Q8 + 255) / 256), 256>>>(
        lstm_Wih, lstm_Whh, lstm_bih, lstm_bhh,
        W_ih, W_hh, b_ih, x_t, h_lstm, Wq, Wk, Wv);

    GArgs a;
    // q = x @ Wq.T  (trunc store, feeds kq)
    a = {}; a.mode = 0; a.K = 256; a.lda = 256; a.ldw = 256; a.ldc = 512;
    a.trunc_out = 1; a.A = p_xtf; a.W = p_wqtf; a.C = p_q;
    launch_g(a, BB, HH);
    // kq = q @ Wk
    a = {}; a.mode = 0; a.K = 512; a.lda = 512; a.ldw = 512; a.ldc = 256;
    a.A = p_q; a.W = p_wkT; a.C = p_kq;
    launch_g(a, BB, DD);
    // v = x @ Wv.T + bv
    a = {}; a.mode = 0; a.K = 256; a.lda = 256; a.ldw = 256; a.ldc = 256;
    a.A = p_xtf; a.W = p_wvtf; a.bias = bv; a.C = p_v;
    launch_g(a, BB, DD);

    select_idx_kernel<<<BB, NSLOT>>>(slots, filled);
    {
        size_t tot = (size_t)BB * NSLOT * DD;
        update_write_kernel<<<(unsigned)((tot + 255) / 256), 256>>>(
            slots, cum, delta, filled, x_t, out);
    }

    // slot-LSTM recurrence: gates = [h | mem_n] @ [Whh | Wih].T + bias (fused)
    for (int n = 0; n < NSLOT; n++) {
        a = {}; a.mode = 1; a.K = KSTEP; a.ldw = KSTEP; a.ldc = G4;
        a.A  = (n & 1) ? p_h1 : p_h0;
        a.A2 = p_mem + (size_t)n * BB * FEATP;
        a.W = p_wstep; a.bias = p_bias;
        a.c_in = p_c; a.c_out = p_c;
        a.h_tf = (n & 1) ? p_h0 : p_h1;
        a.h_full = (n == NSLOT - 1) ? (out + OFF_HMEM) : nullptr;
        launch_g(a, BB, G4);
    }

    // outer LSTM: K = [x(256) | h_mem(512) | h_lstm(512)]
    a = {}; a.mode = 2; a.K = KOUT; a.ldw = KOUT; a.ldc = G4;
    a.A = p_xtf; a.A2 = p_h0; a.A3 = p_hltf;     // n=63 (odd) wrote h_tf -> p_h0
    a.W = p_wout; a.bias = p_biaso;
    a.c_in = c_lstm; a.c_out = out + OFF_C; a.h_full = out + OFF_H;
    launch_g(a, BB, G4);
}

// round 10
// speedup vs baseline: 1.6097x; 1.4648x over previous
#include <cuda_runtime.h>
#include <cuda_fp16.h>
#include <math.h>
#include <stdint.h>

#define BB    2048
#define DD    256
#define HH    512
#define NSLOT 64
#define FEAT  513
#define FEATP 544
#define G4    2048
#define KSTEP 1056          // 512 (h) + 544 (mem)
#define KOUT  1280          // 256 (x) + 512 (h_mem) + 512 (h_lstm)

#define OFF_H      ((size_t)0)
#define OFF_C      ((size_t)1048576)
#define OFF_HMEM   ((size_t)2097152)
#define OFF_SLOTS  ((size_t)3145728)
#define OFF_CUM    ((size_t)36700160)
#define OFF_DELTA  ((size_t)70254592)
#define OFF_FILLED ((size_t)70385664)

// ------------------------------- scratch ------------------------------------
__device__ __half g_qh[BB * HH];                 // q in fp16 (feeds kq)
__device__ float  g_kq[BB * DD];
__device__ float  g_v[BB * DD];
__device__ int    g_idx[BB];
__device__ float  g_bias[G4];                    // permuted bih+bhh
__device__ float  g_biaso[G4];                   // permuted outer b_ih
__device__ __half g_wstep[(size_t)G4 * KSTEP];   // [Whh | Wih] permuted rows
__device__ __half g_wout[(size_t)G4 * KOUT];     // [W_ih | W_hh] permuted rows
__device__ __half g_xh[BB * DD];
__device__ __half g_hlh[BB * HH];
__device__ __half g_wqh[HH * DD];
__device__ __half g_wkT[DD * HH];
__device__ __half g_wvh[DD * DD];
__device__ __half g_mem[(size_t)NSLOT * BB * FEATP];  // mem_seq [n][b][f] fp16
__device__ __half g_h0[BB * HH];                 // h ping (fp16)
__device__ __half g_h1[BB * HH];                 // h pong (fp16)
__device__ float  g_c[BB * HH];                  // slot-LSTM cell (fp32)
__device__ int    g_fmode;

__device__ __forceinline__ float sigf(float x) { return 1.0f / (1.0f + __expf(-x)); }
__device__ __forceinline__ float tanh_fast(float x) {
    float t = __expf(-2.0f * fabsf(x));
    float r = (1.0f - t) / (1.0f + t);
    return copysignf(r, x);
}

__device__ __forceinline__ int read_filled(const void* p, size_t i, int m) {
    if (m == 0) return ((const float*)p)[i] != 0.0f;
    if (m == 1) return ((const int*)p)[i] != 0;
    if (m == 2) return ((const unsigned char*)p)[i] != 0;
    return ((const unsigned short*)p)[i] != 0;
}

// ----------------------------- PTX helpers ----------------------------------
__device__ __forceinline__ uint32_t smem_u32(const void* p) {
    uint32_t a;
    asm("{ .reg .u64 t; cvta.to.shared.u64 t, %1; cvt.u32.u64 %0, t; }" : "=r"(a) : "l"(p));
    return a;
}
__device__ __forceinline__ void cpasync16(uint32_t dst, const void* src) {
    asm volatile("cp.async.cg.shared.global [%0], [%1], 16;\n" :: "r"(dst), "l"(src));
}
#define CP_COMMIT() asm volatile("cp.async.commit_group;\n" ::: "memory")
#define CP_WAIT1()  asm volatile("cp.async.wait_group 1;\n" ::: "memory")

__device__ __forceinline__ void mma16(float* c, const uint32_t* A, const uint32_t* B) {
    asm volatile(
        "mma.sync.aligned.m16n8k16.row.col.f32.f16.f16.f32 "
        "{%0,%1,%2,%3}, {%4,%5,%6,%7}, {%8,%9}, {%0,%1,%2,%3};"
        : "+f"(c[0]), "+f"(c[1]), "+f"(c[2]), "+f"(c[3])
        : "r"(A[0]), "r"(A[1]), "r"(A[2]), "r"(A[3]), "r"(B[0]), "r"(B[1]));
}

// ------------------------- fp16 warp-MMA GEMM -------------------------------
// Operands fp16 (pre-converted), accumulate fp32. C = A[M,K] @ W[N,K]^T (+bias).
// mode 0: plain store (float C, or fp16 Ch); mode 1: step LSTM (A=[h|mem_n]);
// mode 2: outer LSTM (A=[x|h_mem|h_lstm]).
#define PADH 40                              // halfs per smem row (32 data + 8 pad)
#define TILE_HALFS (128 * PADH)              // 5120
#define BUF_HALFS  (2 * TILE_HALFS)          // A + B
#define SMEM_DYN   67584                     // max(3*20480, 128*132*4 gates)

struct GArgs {
    int mode, K, lda, ldw, ldc;
    const __half *A, *A2, *A3, *W;
    const float *bias, *c_in;
    float *C, *c_out, *h_full;
    __half *Ch, *h_tf;
};

__device__ __forceinline__ void load_stage(uint32_t smb, const GArgs& a,
                                           int bm, int bn, int k0, int tid, int buf) {
    const uint32_t base = smb + (uint32_t)buf * BUF_HALFS * 2;
    const __half* Asrc; int lda, ka;
    if (a.mode == 1) {
        if (k0 < 512) { Asrc = a.A;  lda = 512;   ka = k0; }
        else          { Asrc = a.A2; lda = FEATP; ka = k0 - 512; }
    } else if (a.mode == 2) {
        if (k0 < 256)      { Asrc = a.A;  lda = 256; ka = k0; }
        else if (k0 < 768) { Asrc = a.A2; lda = 512; ka = k0 - 256; }
        else               { Asrc = a.A3; lda = 512; ka = k0 - 768; }
    } else { Asrc = a.A; lda = a.lda; ka = k0; }
    // A tile: 128 rows x 32 halfs = 512 x 16B chunks (4 chunks/row)
#pragma unroll
    for (int i = 0; i < 2; i++) {
        int idx = tid + i * 256;
        int r = idx >> 2, c = idx & 3;
        cpasync16(base + (uint32_t)(r * PADH + c * 8) * 2,
                  Asrc + (size_t)(bm + r) * lda + ka + c * 8);
    }
#pragma unroll
    for (int i = 0; i < 2; i++) {
        int idx = tid + i * 256;
        int r = idx >> 2, c = idx & 3;
        cpasync16(base + (TILE_HALFS + (uint32_t)(r * PADH + c * 8)) * 2,
                  a.W + (size_t)(bn + r) * a.ldw + k0 + c * 8);
    }
}

__global__ void __launch_bounds__(256, 2) mma_gemm_kernel(const GArgs a) {
    extern __shared__ __half smh[];
    const uint32_t smb = smem_u32(smh);

    const int tid = threadIdx.x;
    const int wid = tid >> 5, lane = tid & 31;
    const int wm = wid & 3, wn = wid >> 2;
    const int gid = lane >> 2, tg = lane & 3;
    const int bm = blockIdx.y * 128;
    const int bn = blockIdx.x * 128;

    float acc[2][8][4];
#pragma unroll
    for (int mt = 0; mt < 2; mt++)
#pragma unroll
        for (int nt = 0; nt < 8; nt++)
#pragma unroll
            for (int e = 0; e < 4; e++) acc[mt][nt][e] = 0.0f;

    const int KT = a.K >> 5;
    load_stage(smb, a, bm, bn, 0, tid, 0);
    CP_COMMIT();
    if (KT > 1) load_stage(smb, a, bm, bn, 32, tid, 1);
    CP_COMMIT();

    for (int kt = 0; kt < KT; kt++) {
        CP_WAIT1();
        __syncthreads();
        if (kt + 2 < KT)
            load_stage(smb, a, bm, bn, (kt + 2) * 32, tid, (kt + 2) % 3);
        CP_COMMIT();

        const __half* As = smh + (kt % 3) * BUF_HALFS;
        const __half* Bs = As + TILE_HALFS;
#pragma unroll
        for (int blk = 0; blk < 2; blk++) {
            const int kb = blk * 16;
            uint32_t af[2][4];
#pragma unroll
            for (int mt = 0; mt < 2; mt++) {
                int r0 = wm * 32 + mt * 16 + gid;
                af[mt][0] = *(const uint32_t*)(As + r0 * PADH + kb + 2 * tg);
                af[mt][1] = *(const uint32_t*)(As + (r0 + 8) * PADH + kb + 2 * tg);
                af[mt][2] = *(const uint32_t*)(As + r0 * PADH + kb + 2 * tg + 8);
                af[mt][3] = *(const uint32_t*)(As + (r0 + 8) * PADH + kb + 2 * tg + 8);
            }
            uint32_t bf[8][2];
#pragma unroll
            for (int nt = 0; nt < 8; nt++) {
                int n0 = wn * 64 + nt * 8 + gid;
                bf[nt][0] = *(const uint32_t*)(Bs + n0 * PADH + kb + 2 * tg);
                bf[nt][1] = *(const uint32_t*)(Bs + n0 * PADH + kb + 2 * tg + 8);
            }
#pragma unroll
            for (int mt = 0; mt < 2; mt++)
#pragma unroll
                for (int nt = 0; nt < 8; nt++)
                    mma16(acc[mt][nt], af[mt], bf[nt]);
        }
        __syncthreads();
    }

    if (a.mode == 0) {
#pragma unroll
        for (int mt = 0; mt < 2; mt++) {
            const size_t r0 = (size_t)bm + wm * 32 + mt * 16 + gid;
            const size_t r1 = r0 + 8;
#pragma unroll
            for (int nt = 0; nt < 8; nt++) {
                const int col = bn + wn * 64 + nt * 8 + tg * 2;
                float2 v0 = make_float2(acc[mt][nt][0], acc[mt][nt][1]);
                float2 v1 = make_float2(acc[mt][nt][2], acc[mt][nt][3]);
                if (a.bias) {
                    float2 b2 = *(const float2*)(a.bias + col);
                    v0.x += b2.x; v0.y += b2.y; v1.x += b2.x; v1.y += b2.y;
                }
                if (a.Ch) {
                    *(__half2*)(a.Ch + r0 * a.ldc + col) = __floats2half2_rn(v0.x, v0.y);
                    *(__half2*)(a.Ch + r1 * a.ldc + col) = __floats2half2_rn(v1.x, v1.y);
                } else {
                    *(float2*)(a.C + r0 * a.ldc + col) = v0;
                    *(float2*)(a.C + r1 * a.ldc + col) = v1;
                }
            }
        }
    } else {
        // fused LSTM epilogue (gate columns permuted 4j+t)
        float* gsm = (float*)smh;
#pragma unroll
        for (int mt = 0; mt < 2; mt++) {
            const int lr0 = wm * 32 + mt * 16 + gid;
            const int lr1 = lr0 + 8;
#pragma unroll
            for (int nt = 0; nt < 8; nt++) {
                const int lc = wn * 64 + nt * 8 + tg * 2;
                float2 v0 = make_float2(acc[mt][nt][0], acc[mt][nt][1]);
                float2 v1 = make_float2(acc[mt][nt][2], acc[mt][nt][3]);
                if (a.bias) {
                    float2 b2 = *(const float2*)(a.bias + bn + lc);
                    v0.x += b2.x; v0.y += b2.y; v1.x += b2.x; v1.y += b2.y;
                }
                *(float2*)&gsm[lr0 * 132 + lc] = v0;
                *(float2*)&gsm[lr1 * 132 + lc] = v1;
            }
        }
        __syncthreads();
        const int jb = bn >> 2;
#pragma unroll
        for (int it = 0; it < 16; it++) {
            int idx = tid + it * 256;
            int row = idx >> 5, u = idx & 31;
            float4 gt = *(float4*)&gsm[row * 132 + 4 * u];
            float ii = sigf(gt.x), ff = sigf(gt.y);
            float gg = tanh_fast(gt.z), oo = sigf(gt.w);
            size_t e = (size_t)(bm + row) * HH + jb + u;
            float c_new = ff * a.c_in[e] + ii * gg;
            float h_new = oo * tanh_fast(c_new);
            a.c_out[e] = c_new;
            if (a.h_full) a.h_full[e] = h_new;
            if (a.h_tf)   a.h_tf[e] = __float2half_rn(h_new);
        }
    }
}

static void launch_g(const GArgs& a, int M, int N) {
    static int attr_set = 0;
    if (!attr_set) {
        cudaFuncSetAttribute(mma_gemm_kernel,
                             cudaFuncAttributeMaxDynamicSharedMemorySize, SMEM_DYN);
        attr_set = 1;
    }
    dim3 grid(N / 128, M / 128);
    mma_gemm_kernel<<<grid, 256, SMEM_DYN>>>(a);
}

// ------------------------------ prep kernels --------------------------------
__device__ __forceinline__ int porig(int p) { return ((p & 3) << 9) | (p >> 2); }

#define Q0 ((size_t)G4 * KSTEP)
#define Q1 (Q0 + (size_t)G4 * KOUT)
#define Q2 (Q1 + (size_t)BB * DD)
#define Q3 (Q2 + (size_t)BB * HH)
#define Q4 (Q3 + (size_t)HH * DD)
#define Q5 (Q4 + (size_t)DD * HH)
#define Q6 (Q5 + (size_t)DD * DD)
#define Q7 (Q6 + G4)
#define Q8 (Q7 + G4)

__global__ void prep_kernel(const float* __restrict__ Wih, const float* __restrict__ Whh,
                            const float* __restrict__ bih, const float* __restrict__ bhh,
                            const float* __restrict__ Wiho, const float* __restrict__ Whho,
                            const float* __restrict__ biho,
                            const float* __restrict__ x, const float* __restrict__ hl,
                            const float* __restrict__ Wq, const float* __restrict__ Wk,
                            const float* __restrict__ Wv) {
    size_t e = (size_t)blockIdx.x * blockDim.x + threadIdx.x;
    if (e < Q0) {
        int p = (int)(e / KSTEP), k = (int)(e % KSTEP);
        float v;
        if (k < 512) v = Whh[(size_t)porig(p) * 512 + k];
        else { int f = k - 512; v = (f < FEAT) ? Wih[(size_t)porig(p) * FEAT + f] : 0.0f; }
        g_wstep[e] = __float2half_rn(v);
    } else if (e < Q1) {
        size_t i = e - Q0; int p = (int)(i / KOUT), k = (int)(i % KOUT);
        float v = (k < 768) ? Wiho[(size_t)porig(p) * 768 + k]
                            : Whho[(size_t)porig(p) * 512 + (k - 768)];
        g_wout[i] = __float2half_rn(v);
    } else if (e < Q2) {
        size_t i = e - Q1; g_xh[i] = __float2half_rn(x[i]);
    } else if (e < Q3) {
        size_t i = e - Q2; g_hlh[i] = __float2half_rn(hl[i]);
    } else if (e < Q4) {
        size_t i = e - Q3; g_wqh[i] = __float2half_rn(Wq[i]);
    } else if (e < Q5) {
        size_t i = e - Q4; size_t d = i >> 9, h = i & 511;
        g_wkT[i] = __float2half_rn(Wk[h * 256 + d]);
    } else if (e < Q6) {
        size_t i = e - Q5; g_wvh[i] = __float2half_rn(Wv[i]);
    } else if (e < Q7) {
        int p = (int)(e - Q6); int o = porig(p);
        g_bias[p] = bih[o] + bhh[o];
    } else if (e < Q8) {
        int p = (int)(e - Q7);
        g_biaso[p] = biho[porig(p)];
    }
}

__global__ void zero_hc_kernel() {
    int e = blockIdx.x * blockDim.x + threadIdx.x;
    if (e < BB * HH) { g_h0[e] = __float2half_rn(0.0f); g_c[e] = 0.0f; }
}

__global__ void detect_filled_kernel(const unsigned int* __restrict__ w) {
    __shared__ int flags[3];
    if (threadIdx.x < 3) flags[threadIdx.x] = 0;
    __syncthreads();
    for (int i = threadIdx.x; i < (BB * NSLOT) / 4; i += blockDim.x) {
        unsigned v = w[i];
        if (v == 0x3F800000u)      atomicOr(&flags[0], 1);
        else if (v == 0x3F803F80u) atomicOr(&flags[1], 1);
        else if (v > 1u)           atomicOr(&flags[2], 1);
    }
    __syncthreads();
    if (threadIdx.x == 0) {
        int m;
        if (flags[1])      m = 3;
        else if (flags[0]) m = 0;
        else if (flags[2]) m = 2;
        else               m = 1;
        g_fmode = m;
    }
}

__global__ void select_idx_kernel(const float* __restrict__ slots,
                                  const void* __restrict__ filled) {
    const int b = blockIdx.x;
    const int t = threadIdx.x;
    __shared__ float kq_s[DD];
    __shared__ float sims[NSLOT];
    __shared__ int   emp[NSLOT];
    for (int d = t; d < DD; d += NSLOT) kq_s[d] = g_kq[b * DD + d];
    __syncthreads();
    const float* sp = slots + ((size_t)b * NSLOT + t) * DD;
    float s = 0.0f;
    for (int d = 0; d < DD; d++) s = fmaf(sp[d], kq_s[d], s);
    sims[t] = s;
    emp[t]  = !read_filled(filled, (size_t)b * NSLOT + t, g_fmode);
    __syncthreads();
    if (t == 0) {
        int idx = -1;
        for (int n = 0; n < NSLOT; n++) if (emp[n]) { idx = n; break; }
        if (idx < 0) {
            float best = sims[0]; idx = 0;
            for (int n = 1; n < NSLOT; n++) if (sims[n] > best) { best = sims[n]; idx = n; }
        }
        g_idx[b] = idx;
    }
}

__global__ void update_write_kernel(const float* __restrict__ slots,
                                    const float* __restrict__ cum,
                                    const float* __restrict__ delta,
                                    const void* __restrict__ filled,
                                    const float* __restrict__ x,
                                    float* __restrict__ out) {
    size_t e = (size_t)blockIdx.x * blockDim.x + threadIdx.x;
    if (e >= (size_t)BB * NSLOT * DD) return;
    int d = (int)(e % DD);
    size_t bn = e / DD;
    int n = (int)(bn % NSLOT);
    int b = (int)(bn / NSLOT);
    int idx = g_idx[b];

    float xv = x[b * DD + d];
    float sl = slots[e];
    float cf = cum[e] + xv;
    if (n == idx) { sl = g_v[b * DD + d]; cf = xv; }

    out[OFF_SLOTS + e] = sl;
    out[OFF_CUM + e]   = cf;

    size_t mbase = ((size_t)n * BB + b) * FEATP;
    g_mem[mbase + d]      = __float2half_rn(sl);
    g_mem[mbase + DD + d] = __float2half_rn(cf);
    if (d < FEATP - FEAT) g_mem[mbase + FEAT + d] = __float2half_rn(0.0f);
    if (d == 0) {
        float dt = (n == idx) ? 0.0f : delta[bn] + 1.0f;
        out[OFF_DELTA + bn] = dt;
        g_mem[mbase + 2 * DD] = __float2half_rn(dt);
        int fl = (n == idx) ? 1 : read_filled(filled, bn, g_fmode);
        out[OFF_FILLED + bn] = fl ? 1.0f : 0.0f;
    }
}

// --------------------------------- launch -----------------------------------
extern "C" void kernel_launch(void* const* d_in, const int* in_sizes, int n_in,
                              void* d_out, int out_size) {
    const float* x_t      = (const float*)d_in[0];
    const float* h_lstm   = (const float*)d_in[1];
    const float* c_lstm   = (const float*)d_in[2];
    const float* slots    = (const float*)d_in[4];
    const float* cum      = (const float*)d_in[5];
    const float* delta    = (const float*)d_in[6];
    const void*  filled   = (const void*)d_in[7];
    const float* Wq       = (const float*)d_in[8];
    const float* Wk       = (const float*)d_in[9];
    const float* Wv       = (const float*)d_in[10];
    const float* bv       = (const float*)d_in[11];
    const float* lstm_Wih = (const float*)d_in[12];
    const float* lstm_Whh = (const float*)d_in[13];
    const float* lstm_bih = (const float*)d_in[14];
    const float* lstm_bhh = (const float*)d_in[15];
    const float* W_ih     = (const float*)d_in[16];
    const float* b_ih     = (const float*)d_in[17];
    const float* W_hh     = (const float*)d_in[18];
    float* out = (float*)d_out;

    float *p_kq, *p_v, *p_c, *p_bias, *p_biaso;
    __half *p_qh, *p_mem, *p_wstep, *p_wout, *p_xh, *p_hlh, *p_wqh, *p_wkT, *p_wvh;
    __half *p_h0, *p_h1;
    cudaGetSymbolAddress((void**)&p_qh, g_qh);
    cudaGetSymbolAddress((void**)&p_kq, g_kq);
    cudaGetSymbolAddress((void**)&p_v, g_v);
    cudaGetSymbolAddress((void**)&p_mem, g_mem);
    cudaGetSymbolAddress((void**)&p_c, g_c);
    cudaGetSymbolAddress((void**)&p_bias, g_bias);
    cudaGetSymbolAddress((void**)&p_biaso, g_biaso);
    cudaGetSymbolAddress((void**)&p_wstep, g_wstep);
    cudaGetSymbolAddress((void**)&p_wout, g_wout);
    cudaGetSymbolAddress((void**)&p_xh, g_xh);
    cudaGetSymbolAddress((void**)&p_hlh, g_hlh);
    cudaGetSymbolAddress((void**)&p_wqh, g_wqh);
    cudaGetSymbolAddress((void**)&p_wkT, g_wkT);
    cudaGetSymbolAddress((void**)&p_wvh, g_wvh);
    cudaGetSymbolAddress((void**)&p_h0, g_h0);
    cudaGetSymbolAddress((void**)&p_h1, g_h1);

    detect_filled_kernel<<<1, 256>>>((const unsigned int*)filled);
    zero_hc_kernel<<<(BB * HH + 255) / 256, 256>>>();
    prep_kernel<<<(unsigned)((Q8 + 255) / 256), 256>>>(
        lstm_Wih, lstm_Whh, lstm_bih, lstm_bhh,
        W_ih, W_hh, b_ih, x_t, h_lstm, Wq, Wk, Wv);

    GArgs a;
    // q = x @ Wq.T  (fp16 store, feeds kq)
    a = {}; a.mode = 0; a.K = 256; a.lda = 256; a.ldw = 256; a.ldc = 512;
    a.A = p_xh; a.W = p_wqh; a.Ch = p_qh;
    launch_g(a, BB, HH);
    // kq = q @ Wk
    a = {}; a.mode = 0; a.K = 512; a.lda = 512; a.ldw = 512; a.ldc = 256;
    a.A = p_qh; a.W = p_wkT; a.C = p_kq;
    launch_g(a, BB, DD);
    // v = x @ Wv.T + bv
    a = {}; a.mode = 0; a.K = 256; a.lda = 256; a.ldw = 256; a.ldc = 256;
    a.A = p_xh; a.W = p_wvh; a.bias = bv; a.C = p_v;
    launch_g(a, BB, DD);

    select_idx_kernel<<<BB, NSLOT>>>(slots, filled);
    {
        size_t tot = (size_t)BB * NSLOT * DD;
        update_write_kernel<<<(unsigned)((tot + 255) / 256), 256>>>(
            slots, cum, delta, filled, x_t, out);
    }

    // slot-LSTM recurrence: gates = [h | mem_n] @ [Whh | Wih].T + bias (fused)
    for (int n = 0; n < NSLOT; n++) {
        a = {}; a.mode = 1; a.K = KSTEP; a.ldw = KSTEP; a.ldc = G4;
        a.A  = (n & 1) ? p_h1 : p_h0;
        a.A2 = p_mem + (size_t)n * BB * FEATP;
        a.W = p_wstep; a.bias = p_bias;
        a.c_in = p_c; a.c_out = p_c;
        a.h_tf = (n & 1) ? p_h0 : p_h1;
        a.h_full = (n == NSLOT - 1) ? (out + OFF_HMEM) : nullptr;
        launch_g(a, BB, G4);
    }

    // outer LSTM: K = [x(256) | h_mem(512) | h_lstm(512)]
    a = {}; a.mode = 2; a.K = KOUT; a.ldw = KOUT; a.ldc = G4;
    a.A = p_xh; a.A2 = p_h0; a.A3 = p_hlh;      // n=63 (odd) wrote h_tf -> p_h0
    a.W = p_wout; a.bias = p_biaso;
    a.c_in = c_lstm; a.c_out = out + OFF_C; a.h_full = out + OFF_H;
    launch_g(a, BB, G4);
}

// round 11
// speedup vs baseline: 1.7679x; 1.0982x over previous
#include <cuda_runtime.h>
#include <cuda_fp16.h>
#include <math.h>
#include <stdint.h>

#define BB    2048
#define DD    256
#define HH    512
#define NSLOT 64
#define FEAT  513
#define FEATP 576           // padded to multiple of 64
#define G4    2048
#define KSTEP 1088          // 512 (h) + 576 (mem)
#define KOUT  1280          // 256 (x) + 512 (h_mem) + 512 (h_lstm)

#define OFF_H      ((size_t)0)
#define OFF_C      ((size_t)1048576)
#define OFF_HMEM   ((size_t)2097152)
#define OFF_SLOTS  ((size_t)3145728)
#define OFF_CUM    ((size_t)36700160)
#define OFF_DELTA  ((size_t)70254592)
#define OFF_FILLED ((size_t)70385664)

// ------------------------------- scratch ------------------------------------
__device__ __half g_qh[BB * HH];
__device__ float  g_kq[BB * DD];
__device__ float  g_v[BB * DD];
__device__ int    g_idx[BB];
__device__ float  g_bias[G4];
__device__ float  g_biaso[G4];
__device__ __half g_wstep[(size_t)G4 * KSTEP];
__device__ __half g_wout[(size_t)G4 * KOUT];
__device__ __half g_xh[BB * DD];
__device__ __half g_hlh[BB * HH];
__device__ __half g_wqh[HH * DD];
__device__ __half g_wkT[DD * HH];
__device__ __half g_wvh[DD * DD];
__device__ __half g_mem[(size_t)NSLOT * BB * FEATP];
__device__ __half g_h0[BB * HH];
__device__ __half g_h1[BB * HH];
__device__ float  g_c[BB * HH];
__device__ int    g_barc[NSLOT];          // chain barrier counters
__device__ int    g_fmode;

__device__ __forceinline__ float sigf(float x) { return 1.0f / (1.0f + __expf(-x)); }
__device__ __forceinline__ float tanh_fast(float x) {
    float t = __expf(-2.0f * fabsf(x));
    float r = (1.0f - t) / (1.0f + t);
    return copysignf(r, x);
}

__device__ __forceinline__ int read_filled(const void* p, size_t i, int m) {
    if (m == 0) return ((const float*)p)[i] != 0.0f;
    if (m == 1) return ((const int*)p)[i] != 0;
    if (m == 2) return ((const unsigned char*)p)[i] != 0;
    return ((const unsigned short*)p)[i] != 0;
}

// ----------------------------- PTX helpers ----------------------------------
__device__ __forceinline__ uint32_t smem_u32(const void* p) {
    uint32_t a;
    asm("{ .reg .u64 t; cvta.to.shared.u64 t, %1; cvt.u32.u64 %0, t; }" : "=r"(a) : "l"(p));
    return a;
}
__device__ __forceinline__ void cpasync16(uint32_t dst, const void* src) {
    asm volatile("cp.async.cg.shared.global [%0], [%1], 16;\n" :: "r"(dst), "l"(src));
}
#define CP_COMMIT() asm volatile("cp.async.commit_group;\n" ::: "memory")
#define CP_WAIT1()  asm volatile("cp.async.wait_group 1;\n" ::: "memory")

__device__ __forceinline__ void mma16(float* c, const uint32_t* A, const uint32_t* B) {
    asm volatile(
        "mma.sync.aligned.m16n8k16.row.col.f32.f16.f16.f32 "
        "{%0,%1,%2,%3}, {%4,%5,%6,%7}, {%8,%9}, {%0,%1,%2,%3};"
        : "+f"(c[0]), "+f"(c[1]), "+f"(c[2]), "+f"(c[3])
        : "r"(A[0]), "r"(A[1]), "r"(A[2]), "r"(A[3]), "r"(B[0]), "r"(B[1]));
}

// ------------------------- fp16 warp-MMA GEMM core --------------------------
#define PADH 72                              // 64 data halfs + 8 pad
#define TILE_HALFS (128 * PADH)              // 9216
#define BUF_HALFS  (2 * TILE_HALFS)          // 18432 halfs = 36864 B
#define SMEM_DYN   (3 * BUF_HALFS * 2)       // 110592 B

struct Seg {                                  // segmented A operand (<=3 pieces)
    const __half *p0, *p1, *p2;
    int l0, l1, l2, e0, e1;
};

__device__ __forceinline__ void load_stage64(uint32_t smb, const Seg& s,
                                             const __half* W, int ldw,
                                             int bm, int bn, int k0, int tid, int buf) {
    const uint32_t base = smb + (uint32_t)buf * BUF_HALFS * 2;
    const __half* Ap; int lda, ka;
    if (k0 < s.e0)      { Ap = s.p0; lda = s.l0; ka = k0; }
    else if (k0 < s.e1) { Ap = s.p1; lda = s.l1; ka = k0 - s.e0; }
    else                { Ap = s.p2; lda = s.l2; ka = k0 - s.e1; }
#pragma unroll
    for (int i = 0; i < 4; i++) {
        int idx = tid + i * 256;
        int r = idx >> 3, c = idx & 7;
        cpasync16(base + (uint32_t)(r * PADH + c * 8) * 2,
                  Ap + (size_t)(bm + r) * lda + ka + c * 8);
    }
#pragma unroll
    for (int i = 0; i < 4; i++) {
        int idx = tid + i * 256;
        int r = idx >> 3, c = idx & 7;
        cpasync16(base + (TILE_HALFS + (uint32_t)(r * PADH + c * 8)) * 2,
                  W + (size_t)(bn + r) * ldw + k0 + c * 8);
    }
}

__device__ __forceinline__ void gemm_loop(const __half* smh, uint32_t smb,
                                          const Seg& s, const __half* W, int ldw,
                                          int K, int bm, int bn, int tid,
                                          float acc[2][8][4]) {
    const int wid = tid >> 5, lane = tid & 31;
    const int wm = wid & 3, wn = wid >> 2;
    const int gid = lane >> 2, tg = lane & 3;
#pragma unroll
    for (int mt = 0; mt < 2; mt++)
#pragma unroll
        for (int nt = 0; nt < 8; nt++)
#pragma unroll
            for (int e = 0; e < 4; e++) acc[mt][nt][e] = 0.0f;

    const int KT = K >> 6;
    load_stage64(smb, s, W, ldw, bm, bn, 0, tid, 0);
    CP_COMMIT();
    if (KT > 1) load_stage64(smb, s, W, ldw, bm, bn, 64, tid, 1);
    CP_COMMIT();

    for (int kt = 0; kt < KT; kt++) {
        CP_WAIT1();
        __syncthreads();
        if (kt + 2 < KT)
            load_stage64(smb, s, W, ldw, bm, bn, (kt + 2) * 64, tid, (kt + 2) % 3);
        CP_COMMIT();

        const __half* As = smh + (kt % 3) * BUF_HALFS;
        const __half* Bs = As + TILE_HALFS;
#pragma unroll
        for (int blk = 0; blk < 4; blk++) {
            const int kb = blk * 16;
            uint32_t af[2][4];
#pragma unroll
            for (int mt = 0; mt < 2; mt++) {
                int r0 = wm * 32 + mt * 16 + gid;
                af[mt][0] = *(const uint32_t*)(As + r0 * PADH + kb + 2 * tg);
                af[mt][1] = *(const uint32_t*)(As + (r0 + 8) * PADH + kb + 2 * tg);
                af[mt][2] = *(const uint32_t*)(As + r0 * PADH + kb + 2 * tg + 8);
                af[mt][3] = *(const uint32_t*)(As + (r0 + 8) * PADH + kb + 2 * tg + 8);
            }
            uint32_t bf[8][2];
#pragma unroll
            for (int nt = 0; nt < 8; nt++) {
                int n0 = wn * 64 + nt * 8 + gid;
                bf[nt][0] = *(const uint32_t*)(Bs + n0 * PADH + kb + 2 * tg);
                bf[nt][1] = *(const uint32_t*)(Bs + n0 * PADH + kb + 2 * tg + 8);
            }
#pragma unroll
            for (int mt = 0; mt < 2; mt++)
#pragma unroll
                for (int nt = 0; nt < 8; nt++)
                    mma16(acc[mt][nt], af[mt], bf[nt]);
        }
        __syncthreads();
    }
}

// fused LSTM pointwise epilogue (gate columns permuted 4j+t)
__device__ __forceinline__ void lstm_epilogue(float acc[2][8][4], float* gsm,
                                              const float* bias, const float* c_in,
                                              float* c_out, float* h_full, __half* h_tf,
                                              int bm, int bn, int tid) {
    const int wid = tid >> 5, lane = tid & 31;
    const int wm = wid & 3, wn = wid >> 2;
    const int gid = lane >> 2, tg = lane & 3;
#pragma unroll
    for (int mt = 0; mt < 2; mt++) {
        const int lr0 = wm * 32 + mt * 16 + gid;
        const int lr1 = lr0 + 8;
#pragma unroll
        for (int nt = 0; nt < 8; nt++) {
            const int lc = wn * 64 + nt * 8 + tg * 2;
            float2 v0 = make_float2(acc[mt][nt][0], acc[mt][nt][1]);
            float2 v1 = make_float2(acc[mt][nt][2], acc[mt][nt][3]);
            float2 b2 = *(const float2*)(bias + bn + lc);
            v0.x += b2.x; v0.y += b2.y; v1.x += b2.x; v1.y += b2.y;
            *(float2*)&gsm[lr0 * 132 + lc] = v0;
            *(float2*)&gsm[lr1 * 132 + lc] = v1;
        }
    }
    __syncthreads();
    const int jb = bn >> 2;
#pragma unroll
    for (int it = 0; it < 16; it++) {
        int idx = tid + it * 256;
        int row = idx >> 5, u = idx & 31;
        float4 gt = *(float4*)&gsm[row * 132 + 4 * u];
        float ii = sigf(gt.x), ff = sigf(gt.y);
        float gg = tanh_fast(gt.z), oo = sigf(gt.w);
        size_t e = (size_t)(bm + row) * HH + jb + u;
        float c_new = ff * c_in[e] + ii * gg;
        float h_new = oo * tanh_fast(c_new);
        c_out[e] = c_new;
        if (h_full) h_full[e] = h_new;
        if (h_tf)   h_tf[e] = __float2half_rn(h_new);
    }
}

// ---------------------- persistent slot-LSTM chain kernel -------------------
struct ChainArgs {
    const __half *mem, *W;
    const float *bias;
    __half *h0, *h1;
    float *c, *hmem_out;
};

__global__ void __launch_bounds__(256, 2) chain_kernel(const ChainArgs ca) {
    extern __shared__ __half smh[];
    const uint32_t smb = smem_u32(smh);
    const int tid = threadIdx.x;
    const int bm = (blockIdx.x >> 4) * 128;
    const int bn = (blockIdx.x & 15) * 128;
    float acc[2][8][4];

    for (int n = 0; n < NSLOT; n++) {
        Seg s;
        s.p0 = (n & 1) ? ca.h1 : ca.h0; s.l0 = HH; s.e0 = HH;
        s.p1 = ca.mem + (size_t)n * BB * FEATP; s.l1 = FEATP; s.e1 = KSTEP;
        s.p2 = nullptr; s.l2 = 0;
        gemm_loop(smh, smb, s, ca.W, KSTEP, KSTEP, bm, bn, tid, acc);

        lstm_epilogue(acc, (float*)smh, ca.bias, ca.c, ca.c,
                      (n == NSLOT - 1) ? ca.hmem_out : nullptr,
                      (n & 1) ? ca.h0 : ca.h1, bm, bn, tid);

        // grid-wide barrier: release h/c writes, arrive, spin, acquire
        __threadfence();
        __syncthreads();
        if (tid == 0) {
            atomicAdd(&g_barc[n], 1);
            volatile int* bp = &g_barc[n];
            while (*bp < 256) __nanosleep(64);
        }
        __syncthreads();
        __threadfence();
    }
}

// ------------------------- standalone GEMM kernel ----------------------------
struct GArgs {
    int lstm, K, ldw, ldc;
    Seg s;
    const __half *W;
    const float *bias, *c_in;
    float *C, *c_out, *h_full;
    __half *Ch;
};

__global__ void __launch_bounds__(256, 2) mma_gemm_kernel(const GArgs a) {
    extern __shared__ __half smh[];
    const uint32_t smb = smem_u32(smh);
    const int tid = threadIdx.x;
    const int wid = tid >> 5, lane = tid & 31;
    const int wm = wid & 3, wn = wid >> 2;
    const int gid = lane >> 2, tg = lane & 3;
    const int bm = blockIdx.y * 128;
    const int bn = blockIdx.x * 128;
    float acc[2][8][4];

    gemm_loop(smh, smb, a.s, a.W, a.ldw, a.K, bm, bn, tid, acc);

    if (a.lstm) {
        lstm_epilogue(acc, (float*)smh, a.bias, a.c_in, a.c_out, a.h_full,
                      nullptr, bm, bn, tid);
        return;
    }
#pragma unroll
    for (int mt = 0; mt < 2; mt++) {
        const size_t r0 = (size_t)bm + wm * 32 + mt * 16 + gid;
        const size_t r1 = r0 + 8;
#pragma unroll
        for (int nt = 0; nt < 8; nt++) {
            const int col = bn + wn * 64 + nt * 8 + tg * 2;
            float2 v0 = make_float2(acc[mt][nt][0], acc[mt][nt][1]);
            float2 v1 = make_float2(acc[mt][nt][2], acc[mt][nt][3]);
            if (a.bias) {
                float2 b2 = *(const float2*)(a.bias + col);
                v0.x += b2.x; v0.y += b2.y; v1.x += b2.x; v1.y += b2.y;
            }
            if (a.Ch) {
                *(__half2*)(a.Ch + r0 * a.ldc + col) = __floats2half2_rn(v0.x, v0.y);
                *(__half2*)(a.Ch + r1 * a.ldc + col) = __floats2half2_rn(v1.x, v1.y);
            } else {
                *(float2*)(a.C + r0 * a.ldc + col) = v0;
                *(float2*)(a.C + r1 * a.ldc + col) = v1;
            }
        }
    }
}

static void launch_g(const GArgs& a, int M, int N) {
    dim3 grid(N / 128, M / 128);
    mma_gemm_kernel<<<grid, 256, SMEM_DYN>>>(a);
}

// ------------------------------ prep kernels --------------------------------
__device__ __forceinline__ int porig(int p) { return ((p & 3) << 9) | (p >> 2); }

#define Q0 ((size_t)G4 * KSTEP)
#define Q1 (Q0 + (size_t)G4 * KOUT)
#define Q2 (Q1 + (size_t)BB * DD)
#define Q3 (Q2 + (size_t)BB * HH)
#define Q4 (Q3 + (size_t)HH * DD)
#define Q5 (Q4 + (size_t)DD * HH)
#define Q6 (Q5 + (size_t)DD * DD)
#define Q7 (Q6 + G4)
#define Q8 (Q7 + G4)

__global__ void prep_kernel(const float* __restrict__ Wih, const float* __restrict__ Whh,
                            const float* __restrict__ bih, const float* __restrict__ bhh,
                            const float* __restrict__ Wiho, const float* __restrict__ Whho,
                            const float* __restrict__ biho,
                            const float* __restrict__ x, const float* __restrict__ hl,
                            const float* __restrict__ Wq, const float* __restrict__ Wk,
                            const float* __restrict__ Wv) {
    size_t e = (size_t)blockIdx.x * blockDim.x + threadIdx.x;
    if (e < Q0) {
        int p = (int)(e / KSTEP), k = (int)(e % KSTEP);
        float v;
        if (k < 512) v = Whh[(size_t)porig(p) * 512 + k];
        else { int f = k - 512; v = (f < FEAT) ? Wih[(size_t)porig(p) * FEAT + f] : 0.0f; }
        g_wstep[e] = __float2half_rn(v);
    } else if (e < Q1) {
        size_t i = e - Q0; int p = (int)(i / KOUT), k = (int)(i % KOUT);
        float v = (k < 768) ? Wiho[(size_t)porig(p) * 768 + k]
                            : Whho[(size_t)porig(p) * 512 + (k - 768)];
        g_wout[i] = __float2half_rn(v);
    } else if (e < Q2) {
        size_t i = e - Q1; g_xh[i] = __float2half_rn(x[i]);
    } else if (e < Q3) {
        size_t i = e - Q2; g_hlh[i] = __float2half_rn(hl[i]);
    } else if (e < Q4) {
        size_t i = e - Q3; g_wqh[i] = __float2half_rn(Wq[i]);
    } else if (e < Q5) {
        size_t i = e - Q4; size_t d = i >> 9, h = i & 511;
        g_wkT[i] = __float2half_rn(Wk[h * 256 + d]);
    } else if (e < Q6) {
        size_t i = e - Q5; g_wvh[i] = __float2half_rn(Wv[i]);
    } else if (e < Q7) {
        int p = (int)(e - Q6); int o = porig(p);
        g_bias[p] = bih[o] + bhh[o];
    } else if (e < Q8) {
        int p = (int)(e - Q7);
        g_biaso[p] = biho[porig(p)];
    }
}

__global__ void zero_hc_kernel() {
    int e = blockIdx.x * blockDim.x + threadIdx.x;
    if (e < BB * HH) { g_h0[e] = __float2half_rn(0.0f); g_c[e] = 0.0f; }
    if (e < NSLOT) g_barc[e] = 0;
}

__global__ void detect_filled_kernel(const unsigned int* __restrict__ w) {
    __shared__ int flags[3];
    if (threadIdx.x < 3) flags[threadIdx.x] = 0;
    __syncthreads();
    for (int i = threadIdx.x; i < (BB * NSLOT) / 4; i += blockDim.x) {
        unsigned v = w[i];
        if (v == 0x3F800000u)      atomicOr(&flags[0], 1);
        else if (v == 0x3F803F80u) atomicOr(&flags[1], 1);
        else if (v > 1u)           atomicOr(&flags[2], 1);
    }
    __syncthreads();
    if (threadIdx.x == 0) {
        int m;
        if (flags[1])      m = 3;
        else if (flags[0]) m = 0;
        else if (flags[2]) m = 2;
        else               m = 1;
        g_fmode = m;
    }
}

__global__ void select_idx_kernel(const float* __restrict__ slots,
                                  const void* __restrict__ filled) {
    const int b = blockIdx.x;
    const int t = threadIdx.x;
    __shared__ float kq_s[DD];
    __shared__ float sims[NSLOT];
    __shared__ int   emp[NSLOT];
    for (int d = t; d < DD; d += NSLOT) kq_s[d] = g_kq[b * DD + d];
    __syncthreads();
    const float* sp = slots + ((size_t)b * NSLOT + t) * DD;
    float s = 0.0f;
    for (int d = 0; d < DD; d++) s = fmaf(sp[d], kq_s[d], s);
    sims[t] = s;
    emp[t]  = !read_filled(filled, (size_t)b * NSLOT + t, g_fmode);
    __syncthreads();
    if (t == 0) {
        int idx = -1;
        for (int n = 0; n < NSLOT; n++) if (emp[n]) { idx = n; break; }
        if (idx < 0) {
            float best = sims[0]; idx = 0;
            for (int n = 1; n < NSLOT; n++) if (sims[n] > best) { best = sims[n]; idx = n; }
        }
        g_idx[b] = idx;
    }
}

__global__ void update_write_kernel(const float* __restrict__ slots,
                                    const float* __restrict__ cum,
                                    const float* __restrict__ delta,
                                    const void* __restrict__ filled,
                                    const float* __restrict__ x,
                                    float* __restrict__ out) {
    size_t e = (size_t)blockIdx.x * blockDim.x + threadIdx.x;
    if (e >= (size_t)BB * NSLOT * DD) return;
    int d = (int)(e % DD);
    size_t bn = e / DD;
    int n = (int)(bn % NSLOT);
    int b = (int)(bn / NSLOT);
    int idx = g_idx[b];

    float xv = x[b * DD + d];
    float sl = slots[e];
    float cf = cum[e] + xv;
    if (n == idx) { sl = g_v[b * DD + d]; cf = xv; }

    out[OFF_SLOTS + e] = sl;
    out[OFF_CUM + e]   = cf;

    size_t mbase = ((size_t)n * BB + b) * FEATP;
    g_mem[mbase + d]      = __float2half_rn(sl);
    g_mem[mbase + DD + d] = __float2half_rn(cf);
    if (d < FEATP - FEAT) g_mem[mbase + FEAT + d] = __float2half_rn(0.0f);
    if (d == 0) {
        float dt = (n == idx) ? 0.0f : delta[bn] + 1.0f;
        out[OFF_DELTA + bn] = dt;
        g_mem[mbase + 2 * DD] = __float2half_rn(dt);
        int fl = (n == idx) ? 1 : read_filled(filled, bn, g_fmode);
        out[OFF_FILLED + bn] = fl ? 1.0f : 0.0f;
    }
}

// --------------------------------- launch -----------------------------------
extern "C" void kernel_launch(void* const* d_in, const int* in_sizes, int n_in,
                              void* d_out, int out_size) {
    const float* x_t      = (const float*)d_in[0];
    const float* h_lstm   = (const float*)d_in[1];
    const float* c_lstm   = (const float*)d_in[2];
    const float* slots    = (const float*)d_in[4];
    const float* cum      = (const float*)d_in[5];
    const float* delta    = (const float*)d_in[6];
    const void*  filled   = (const void*)d_in[7];
    const float* Wq       = (const float*)d_in[8];
    const float* Wk       = (const float*)d_in[9];
    const float* Wv       = (const float*)d_in[10];
    const float* bv       = (const float*)d_in[11];
    const float* lstm_Wih = (const float*)d_in[12];
    const float* lstm_Whh = (const float*)d_in[13];
    const float* lstm_bih = (const float*)d_in[14];
    const float* lstm_bhh = (const float*)d_in[15];
    const float* W_ih     = (const float*)d_in[16];
    const float* b_ih     = (const float*)d_in[17];
    const float* W_hh     = (const float*)d_in[18];
    float* out = (float*)d_out;

    float *p_kq, *p_v, *p_c, *p_bias, *p_biaso;
    __half *p_qh, *p_mem, *p_wstep, *p_wout, *p_xh, *p_hlh, *p_wqh, *p_wkT, *p_wvh;
    __half *p_h0, *p_h1;
    cudaGetSymbolAddress((void**)&p_qh, g_qh);
    cudaGetSymbolAddress((void**)&p_kq, g_kq);
    cudaGetSymbolAddress((void**)&p_v, g_v);
    cudaGetSymbolAddress((void**)&p_mem, g_mem);
    cudaGetSymbolAddress((void**)&p_c, g_c);
    cudaGetSymbolAddress((void**)&p_bias, g_bias);
    cudaGetSymbolAddress((void**)&p_biaso, g_biaso);
    cudaGetSymbolAddress((void**)&p_wstep, g_wstep);
    cudaGetSymbolAddress((void**)&p_wout, g_wout);
    cudaGetSymbolAddress((void**)&p_xh, g_xh);
    cudaGetSymbolAddress((void**)&p_hlh, g_hlh);
    cudaGetSymbolAddress((void**)&p_wqh, g_wqh);
    cudaGetSymbolAddress((void**)&p_wkT, g_wkT);
    cudaGetSymbolAddress((void**)&p_wvh, g_wvh);
    cudaGetSymbolAddress((void**)&p_h0, g_h0);
    cudaGetSymbolAddress((void**)&p_h1, g_h1);

    static int attr_set = 0;
    if (!attr_set) {
        cudaFuncSetAttribute(mma_gemm_kernel,
                             cudaFuncAttributeMaxDynamicSharedMemorySize, SMEM_DYN);
        cudaFuncSetAttribute(chain_kernel,
                             cudaFuncAttributeMaxDynamicSharedMemorySize, SMEM_DYN);
        attr_set = 1;
    }

    detect_filled_kernel<<<1, 256>>>((const unsigned int*)filled);
    zero_hc_kernel<<<(BB * HH + 255) / 256, 256>>>();
    prep_kernel<<<(unsigned)((Q8 + 255) / 256), 256>>>(
        lstm_Wih, lstm_Whh, lstm_bih, lstm_bhh,
        W_ih, W_hh, b_ih, x_t, h_lstm, Wq, Wk, Wv);

    GArgs a;
    // q = x @ Wq.T (fp16 store)
    a = {}; a.K = 256; a.ldw = 256; a.ldc = 512;
    a.s = { p_xh, nullptr, nullptr, 256, 0, 0, 256, 256 };
    a.W = p_wqh; a.Ch = p_qh;
    launch_g(a, BB, HH);
    // kq = q @ Wk
    a = {}; a.K = 512; a.ldw = 512; a.ldc = 256;
    a.s = { p_qh, nullptr, nullptr, 512, 0, 0, 512, 512 };
    a.W = p_wkT; a.C = p_kq;
    launch_g(a, BB, DD);
    // v = x @ Wv.T + bv
    a = {}; a.K = 256; a.ldw = 256; a.ldc = 256;
    a.s = { p_xh, nullptr, nullptr, 256, 0, 0, 256, 256 };
    a.W = p_wvh; a.bias = bv; a.C = p_v;
    launch_g(a, BB, DD);

    select_idx_kernel<<<BB, NSLOT>>>(slots, filled);
    {
        size_t tot = (size_t)BB * NSLOT * DD;
        update_write_kernel<<<(unsigned)((tot + 255) / 256), 256>>>(
            slots, cum, delta, filled, x_t, out);
    }

    // persistent slot-LSTM chain: all 64 steps in one launch
    {
        ChainArgs ca;
        ca.mem = p_mem; ca.W = p_wstep; ca.bias = p_bias;
        ca.h0 = p_h0; ca.h1 = p_h1; ca.c = p_c;
        ca.hmem_out = out + OFF_HMEM;
        chain_kernel<<<256, 256, SMEM_DYN>>>(ca);
    }

    // outer LSTM: K = [x(256) | h_mem(512) | h_lstm(512)]
    a = {}; a.lstm = 1; a.K = KOUT; a.ldw = KOUT; a.ldc = G4;
    a.s = { p_xh, p_h0, p_hlh, 256, 512, 512, 256, 768 };   // n=63 odd -> h in p_h0
    a.W = p_wout; a.bias = p_biaso;
    a.c_in = c_lstm; a.c_out = out + OFF_C; a.h_full = out + OFF_H;
    launch_g(a, BB, G4);
}

// round 12
// speedup vs baseline: 1.7689x; 1.0006x over previous
#include <cuda_runtime.h>
#include <cuda_fp16.h>
#include <math.h>
#include <stdint.h>

#define BB    2048
#define DD    256
#define HH    512
#define NSLOT 64
#define FEAT  513
#define FEATP 576           // padded to multiple of 64
#define G4    2048
#define KSTEP 1088          // 512 (h) + 576 (mem)
#define KOUT  1280          // 256 (x) + 512 (h_mem) + 512 (h_lstm)

#define OFF_H      ((size_t)0)
#define OFF_C      ((size_t)1048576)
#define OFF_HMEM   ((size_t)2097152)
#define OFF_SLOTS  ((size_t)3145728)
#define OFF_CUM    ((size_t)36700160)
#define OFF_DELTA  ((size_t)70254592)
#define OFF_FILLED ((size_t)70385664)

// ------------------------------- scratch ------------------------------------
__device__ __half g_qh[BB * HH];
__device__ float  g_kq[BB * DD];
__device__ float  g_v[BB * DD];
__device__ int    g_idx[BB];
__device__ float  g_bias[G4];
__device__ float  g_biaso[G4];
__device__ __half g_wstep[(size_t)G4 * KSTEP];
__device__ __half g_wout[(size_t)G4 * KOUT];
__device__ __half g_xh[BB * DD];
__device__ __half g_hlh[BB * HH];
__device__ __half g_wqh[HH * DD];
__device__ __half g_wkT[DD * HH];
__device__ __half g_wvh[DD * DD];
__device__ __half g_mem[(size_t)NSLOT * BB * FEATP];
__device__ __half g_h0[BB * HH];
__device__ __half g_h1[BB * HH];
__device__ float  g_c[BB * HH];
__device__ int    g_barc[NSLOT];          // chain barrier counters
__device__ int    g_fmode;

__device__ __forceinline__ float sigf(float x) { return 1.0f / (1.0f + __expf(-x)); }
__device__ __forceinline__ float tanh_fast(float x) {
    float t = __expf(-2.0f * fabsf(x));
    float r = (1.0f - t) / (1.0f + t);
    return copysignf(r, x);
}

__device__ __forceinline__ int read_filled(const void* p, size_t i, int m) {
    if (m == 0) return ((const float*)p)[i] != 0.0f;
    if (m == 1) return ((const int*)p)[i] != 0;
    if (m == 2) return ((const unsigned char*)p)[i] != 0;
    return ((const unsigned short*)p)[i] != 0;
}

// ----------------------------- PTX helpers ----------------------------------
__device__ __forceinline__ uint32_t smem_u32(const void* p) {
    uint32_t a;
    asm("{ .reg .u64 t; cvta.to.shared.u64 t, %1; cvt.u32.u64 %0, t; }" : "=r"(a) : "l"(p));
    return a;
}
__device__ __forceinline__ void cpasync16(uint32_t dst, const void* src) {
    asm volatile("cp.async.cg.shared.global [%0], [%1], 16;\n" :: "r"(dst), "l"(src));
}
#define CP_COMMIT() asm volatile("cp.async.commit_group;\n" ::: "memory")
#define CP_WAIT1()  asm volatile("cp.async.wait_group 1;\n" ::: "memory")

__device__ __forceinline__ void mma16(float* c, const uint32_t* A, const uint32_t* B) {
    asm volatile(
        "mma.sync.aligned.m16n8k16.row.col.f32.f16.f16.f32 "
        "{%0,%1,%2,%3}, {%4,%5,%6,%7}, {%8,%9}, {%0,%1,%2,%3};"
        : "+f"(c[0]), "+f"(c[1]), "+f"(c[2]), "+f"(c[3])
        : "r"(A[0]), "r"(A[1]), "r"(A[2]), "r"(A[3]), "r"(B[0]), "r"(B[1]));
}

// ------------------------- fp16 warp-MMA GEMM core --------------------------
#define PADH 72                              // 64 data halfs + 8 pad
#define TILE_HALFS (128 * PADH)              // 9216
#define BUF_HALFS  (2 * TILE_HALFS)          // 18432 halfs = 36864 B
#define SMEM_DYN   (3 * BUF_HALFS * 2)       // 110592 B

struct Seg {                                  // segmented A operand (<=3 pieces)
    const __half *p0, *p1, *p2;
    int l0, l1, l2, e0, e1;
};

__device__ __forceinline__ void load_stage64(uint32_t smb, const Seg& s,
                                             const __half* W, int ldw,
                                             int bm, int bn, int k0, int tid, int buf) {
    const uint32_t base = smb + (uint32_t)buf * BUF_HALFS * 2;
    const __half* Ap; int lda, ka;
    if (k0 < s.e0)      { Ap = s.p0; lda = s.l0; ka = k0; }
    else if (k0 < s.e1) { Ap = s.p1; lda = s.l1; ka = k0 - s.e0; }
    else                { Ap = s.p2; lda = s.l2; ka = k0 - s.e1; }
#pragma unroll
    for (int i = 0; i < 4; i++) {
        int idx = tid + i * 256;
        int r = idx >> 3, c = idx & 7;
        cpasync16(base + (uint32_t)(r * PADH + c * 8) * 2,
                  Ap + (size_t)(bm + r) * lda + ka + c * 8);
    }
#pragma unroll
    for (int i = 0; i < 4; i++) {
        int idx = tid + i * 256;
        int r = idx >> 3, c = idx & 7;
        cpasync16(base + (TILE_HALFS + (uint32_t)(r * PADH + c * 8)) * 2,
                  W + (size_t)(bn + r) * ldw + k0 + c * 8);
    }
}

__device__ __forceinline__ void gemm_loop(const __half* smh, uint32_t smb,
                                          const Seg& s, const __half* W, int ldw,
                                          int K, int bm, int bn, int tid,
                                          float acc[2][8][4]) {
    const int wid = tid >> 5, lane = tid & 31;
    const int wm = wid & 3, wn = wid >> 2;
    const int gid = lane >> 2, tg = lane & 3;
#pragma unroll
    for (int mt = 0; mt < 2; mt++)
#pragma unroll
        for (int nt = 0; nt < 8; nt++)
#pragma unroll
            for (int e = 0; e < 4; e++) acc[mt][nt][e] = 0.0f;

    const int KT = K >> 6;
    load_stage64(smb, s, W, ldw, bm, bn, 0, tid, 0);
    CP_COMMIT();
    if (KT > 1) load_stage64(smb, s, W, ldw, bm, bn, 64, tid, 1);
    CP_COMMIT();

    for (int kt = 0; kt < KT; kt++) {
        CP_WAIT1();
        __syncthreads();
        if (kt + 2 < KT)
            load_stage64(smb, s, W, ldw, bm, bn, (kt + 2) * 64, tid, (kt + 2) % 3);
        CP_COMMIT();

        const __half* As = smh + (kt % 3) * BUF_HALFS;
        const __half* Bs = As + TILE_HALFS;
#pragma unroll
        for (int blk = 0; blk < 4; blk++) {
            const int kb = blk * 16;
            uint32_t af[2][4];
#pragma unroll
            for (int mt = 0; mt < 2; mt++) {
                int r0 = wm * 32 + mt * 16 + gid;
                af[mt][0] = *(const uint32_t*)(As + r0 * PADH + kb + 2 * tg);
                af[mt][1] = *(const uint32_t*)(As + (r0 + 8) * PADH + kb + 2 * tg);
                af[mt][2] = *(const uint32_t*)(As + r0 * PADH + kb + 2 * tg + 8);
                af[mt][3] = *(const uint32_t*)(As + (r0 + 8) * PADH + kb + 2 * tg + 8);
            }
            uint32_t bf[8][2];
#pragma unroll
            for (int nt = 0; nt < 8; nt++) {
                int n0 = wn * 64 + nt * 8 + gid;
                bf[nt][0] = *(const uint32_t*)(Bs + n0 * PADH + kb + 2 * tg);
                bf[nt][1] = *(const uint32_t*)(Bs + n0 * PADH + kb + 2 * tg + 8);
            }
#pragma unroll
            for (int mt = 0; mt < 2; mt++)
#pragma unroll
                for (int nt = 0; nt < 8; nt++)
                    mma16(acc[mt][nt], af[mt], bf[nt]);
        }
        __syncthreads();
    }
}

// fused LSTM pointwise epilogue (gate columns permuted 4j+t)
__device__ __forceinline__ void lstm_epilogue(float acc[2][8][4], float* gsm,
                                              const float* bias, const float* c_in,
                                              float* c_out, float* h_full, __half* h_tf,
                                              int bm, int bn, int tid) {
    const int wid = tid >> 5, lane = tid & 31;
    const int wm = wid & 3, wn = wid >> 2;
    const int gid = lane >> 2, tg = lane & 3;
#pragma unroll
    for (int mt = 0; mt < 2; mt++) {
        const int lr0 = wm * 32 + mt * 16 + gid;
        const int lr1 = lr0 + 8;
#pragma unroll
        for (int nt = 0; nt < 8; nt++) {
            const int lc = wn * 64 + nt * 8 + tg * 2;
            float2 v0 = make_float2(acc[mt][nt][0], acc[mt][nt][1]);
            float2 v1 = make_float2(acc[mt][nt][2], acc[mt][nt][3]);
            float2 b2 = *(const float2*)(bias + bn + lc);
            v0.x += b2.x; v0.y += b2.y; v1.x += b2.x; v1.y += b2.y;
            *(float2*)&gsm[lr0 * 132 + lc] = v0;
            *(float2*)&gsm[lr1 * 132 + lc] = v1;
        }
    }
    __syncthreads();
    const int jb = bn >> 2;
#pragma unroll
    for (int it = 0; it < 16; it++) {
        int idx = tid + it * 256;
        int row = idx >> 5, u = idx & 31;
        float4 gt = *(float4*)&gsm[row * 132 + 4 * u];
        float ii = sigf(gt.x), ff = sigf(gt.y);
        float gg = tanh_fast(gt.z), oo = sigf(gt.w);
        size_t e = (size_t)(bm + row) * HH + jb + u;
        float c_new = ff * c_in[e] + ii * gg;
        float h_new = oo * tanh_fast(c_new);
        c_out[e] = c_new;
        if (h_full) h_full[e] = h_new;
        if (h_tf)   h_tf[e] = __float2half_rn(h_new);
    }
}

// ---------------------- persistent slot-LSTM chain kernel -------------------
struct ChainArgs {
    const __half *mem, *W;
    const float *bias;
    __half *h0, *h1;
    float *c, *hmem_out;
};

__global__ void __launch_bounds__(256, 2) chain_kernel(const ChainArgs ca) {
    extern __shared__ __half smh[];
    const uint32_t smb = smem_u32(smh);
    const int tid = threadIdx.x;
    const int bm = (blockIdx.x >> 4) * 128;
    const int bn = (blockIdx.x & 15) * 128;
    float acc[2][8][4];

    for (int n = 0; n < NSLOT; n++) {
        Seg s;
        s.p0 = (n & 1) ? ca.h1 : ca.h0; s.l0 = HH; s.e0 = HH;
        s.p1 = ca.mem + (size_t)n * BB * FEATP; s.l1 = FEATP; s.e1 = KSTEP;
        s.p2 = nullptr; s.l2 = 0;
        gemm_loop(smh, smb, s, ca.W, KSTEP, KSTEP, bm, bn, tid, acc);

        lstm_epilogue(acc, (float*)smh, ca.bias, ca.c, ca.c,
                      (n == NSLOT - 1) ? ca.hmem_out : nullptr,
                      (n & 1) ? ca.h0 : ca.h1, bm, bn, tid);

        // grid-wide barrier: release h/c writes, arrive, spin, acquire
        __threadfence();
        __syncthreads();
        if (tid == 0) {
            atomicAdd(&g_barc[n], 1);
            volatile int* bp = &g_barc[n];
            while (*bp < 256) __nanosleep(64);
        }
        __syncthreads();
        __threadfence();
    }
}

// ------------------------- standalone GEMM kernel ----------------------------
struct GArgs {
    int lstm, K, ldw, ldc;
    Seg s;
    const __half *W;
    const float *bias, *c_in;
    float *C, *c_out, *h_full;
    __half *Ch;
};

__global__ void __launch_bounds__(256, 2) mma_gemm_kernel(const GArgs a) {
    extern __shared__ __half smh[];
    const uint32_t smb = smem_u32(smh);
    const int tid = threadIdx.x;
    const int wid = tid >> 5, lane = tid & 31;
    const int wm = wid & 3, wn = wid >> 2;
    const int gid = lane >> 2, tg = lane & 3;
    const int bm = blockIdx.y * 128;
    const int bn = blockIdx.x * 128;
    float acc[2][8][4];

    gemm_loop(smh, smb, a.s, a.W, a.ldw, a.K, bm, bn, tid, acc);

    if (a.lstm) {
        lstm_epilogue(acc, (float*)smh, a.bias, a.c_in, a.c_out, a.h_full,
                      nullptr, bm, bn, tid);
        return;
    }
#pragma unroll
    for (int mt = 0; mt < 2; mt++) {
        const size_t r0 = (size_t)bm + wm * 32 + mt * 16 + gid;
        const size_t r1 = r0 + 8;
#pragma unroll
        for (int nt = 0; nt < 8; nt++) {
            const int col = bn + wn * 64 + nt * 8 + tg * 2;
            float2 v0 = make_float2(acc[mt][nt][0], acc[mt][nt][1]);
            float2 v1 = make_float2(acc[mt][nt][2], acc[mt][nt][3]);
            if (a.bias) {
                float2 b2 = *(const float2*)(a.bias + col);
                v0.x += b2.x; v0.y += b2.y; v1.x += b2.x; v1.y += b2.y;
            }
            if (a.Ch) {
                *(__half2*)(a.Ch + r0 * a.ldc + col) = __floats2half2_rn(v0.x, v0.y);
                *(__half2*)(a.Ch + r1 * a.ldc + col) = __floats2half2_rn(v1.x, v1.y);
            } else {
                *(float2*)(a.C + r0 * a.ldc + col) = v0;
                *(float2*)(a.C + r1 * a.ldc + col) = v1;
            }
        }
    }
}

static void launch_g(const GArgs& a, int M, int N) {
    dim3 grid(N / 128, M / 128);
    mma_gemm_kernel<<<grid, 256, SMEM_DYN>>>(a);
}

// ------------------------------ prep kernels --------------------------------
__device__ __forceinline__ int porig(int p) { return ((p & 3) << 9) | (p >> 2); }

#define Q0 ((size_t)G4 * KSTEP)
#define Q1 (Q0 + (size_t)G4 * KOUT)
#define Q2 (Q1 + (size_t)BB * DD)
#define Q3 (Q2 + (size_t)BB * HH)
#define Q4 (Q3 + (size_t)HH * DD)
#define Q5 (Q4 + (size_t)DD * HH)
#define Q6 (Q5 + (size_t)DD * DD)
#define Q7 (Q6 + G4)
#define Q8 (Q7 + G4)

__global__ void prep_kernel(const float* __restrict__ Wih, const float* __restrict__ Whh,
                            const float* __restrict__ bih, const float* __restrict__ bhh,
                            const float* __restrict__ Wiho, const float* __restrict__ Whho,
                            const float* __restrict__ biho,
                            const float* __restrict__ x, const float* __restrict__ hl,
                            const float* __restrict__ Wq, const float* __restrict__ Wk,
                            const float* __restrict__ Wv) {
    size_t e = (size_t)blockIdx.x * blockDim.x + threadIdx.x;
    if (e < Q0) {
        int p = (int)(e / KSTEP), k = (int)(e % KSTEP);
        float v;
        if (k < 512) v = Whh[(size_t)porig(p) * 512 + k];
        else { int f = k - 512; v = (f < FEAT) ? Wih[(size_t)porig(p) * FEAT + f] : 0.0f; }
        g_wstep[e] = __float2half_rn(v);
    } else if (e < Q1) {
        size_t i = e - Q0; int p = (int)(i / KOUT), k = (int)(i % KOUT);
        float v = (k < 768) ? Wiho[(size_t)porig(p) * 768 + k]
                            : Whho[(size_t)porig(p) * 512 + (k - 768)];
        g_wout[i] = __float2half_rn(v);
    } else if (e < Q2) {
        size_t i = e - Q1; g_xh[i] = __float2half_rn(x[i]);
    } else if (e < Q3) {
        size_t i = e - Q2; g_hlh[i] = __float2half_rn(hl[i]);
    } else if (e < Q4) {
        size_t i = e - Q3; g_wqh[i] = __float2half_rn(Wq[i]);
    } else if (e < Q5) {
        size_t i = e - Q4; size_t d = i >> 9, h = i & 511;
        g_wkT[i] = __float2half_rn(Wk[h * 256 + d]);
    } else if (e < Q6) {
        size_t i = e - Q5; g_wvh[i] = __float2half_rn(Wv[i]);
    } else if (e < Q7) {
        int p = (int)(e - Q6); int o = porig(p);
        g_bias[p] = bih[o] + bhh[o];
    } else if (e < Q8) {
        int p = (int)(e - Q7);
        g_biaso[p] = biho[porig(p)];
    }
}

__global__ void zero_hc_kernel() {
    int e = blockIdx.x * blockDim.x + threadIdx.x;
    if (e < BB * HH) { g_h0[e] = __float2half_rn(0.0f); g_c[e] = 0.0f; }
    if (e < NSLOT) g_barc[e] = 0;
}

__global__ void detect_filled_kernel(const unsigned int* __restrict__ w) {
    __shared__ int flags[3];
    if (threadIdx.x < 3) flags[threadIdx.x] = 0;
    __syncthreads();
    for (int i = threadIdx.x; i < (BB * NSLOT) / 4; i += blockDim.x) {
        unsigned v = w[i];
        if (v == 0x3F800000u)      atomicOr(&flags[0], 1);
        else if (v == 0x3F803F80u) atomicOr(&flags[1], 1);
        else if (v > 1u)           atomicOr(&flags[2], 1);
    }
    __syncthreads();
    if (threadIdx.x == 0) {
        int m;
        if (flags[1])      m = 3;
        else if (flags[0]) m = 0;
        else if (flags[2]) m = 2;
        else               m = 1;
        g_fmode = m;
    }
}

__global__ void select_idx_kernel(const float* __restrict__ slots,
                                  const void* __restrict__ filled) {
    const int b = blockIdx.x;
    const int t = threadIdx.x;
    __shared__ float kq_s[DD];
    __shared__ float sims[NSLOT];
    __shared__ int   emp[NSLOT];
    for (int d = t; d < DD; d += NSLOT) kq_s[d] = g_kq[b * DD + d];
    __syncthreads();
    const float* sp = slots + ((size_t)b * NSLOT + t) * DD;
    float s = 0.0f;
    for (int d = 0; d < DD; d++) s = fmaf(sp[d], kq_s[d], s);
    sims[t] = s;
    emp[t]  = !read_filled(filled, (size_t)b * NSLOT + t, g_fmode);
    __syncthreads();
    if (t == 0) {
        int idx = -1;
        for (int n = 0; n < NSLOT; n++) if (emp[n]) { idx = n; break; }
        if (idx < 0) {
            float best = sims[0]; idx = 0;
            for (int n = 1; n < NSLOT; n++) if (sims[n] > best) { best = sims[n]; idx = n; }
        }
        g_idx[b] = idx;
    }
}

__global__ void update_write_kernel(const float* __restrict__ slots,
                                    const float* __restrict__ cum,
                                    const float* __restrict__ delta,
                                    const void* __restrict__ filled,
                                    const float* __restrict__ x,
                                    float* __restrict__ out) {
    size_t e = (size_t)blockIdx.x * blockDim.x + threadIdx.x;
    if (e >= (size_t)BB * NSLOT * DD) return;
    int d = (int)(e % DD);
    size_t bn = e / DD;
    int n = (int)(bn % NSLOT);
    int b = (int)(bn / NSLOT);
    int idx = g_idx[b];

    float xv = x[b * DD + d];
    float sl = slots[e];
    float cf = cum[e] + xv;
    if (n == idx) { sl = g_v[b * DD + d]; cf = xv; }

    out[OFF_SLOTS + e] = sl;
    out[OFF_CUM + e]   = cf;

    size_t mbase = ((size_t)n * BB + b) * FEATP;
    g_mem[mbase + d]      = __float2half_rn(sl);
    g_mem[mbase + DD + d] = __float2half_rn(cf);
    if (d < FEATP - FEAT) g_mem[mbase + FEAT + d] = __float2half_rn(0.0f);
    if (d == 0) {
        float dt = (n == idx) ? 0.0f : delta[bn] + 1.0f;
        out[OFF_DELTA + bn] = dt;
        g_mem[mbase + 2 * DD] = __float2half_rn(dt);
        int fl = (n == idx) ? 1 : read_filled(filled, bn, g_fmode);
        out[OFF_FILLED + bn] = fl ? 1.0f : 0.0f;
    }
}

// --------------------------------- launch -----------------------------------
extern "C" void kernel_launch(void* const* d_in, const int* in_sizes, int n_in,
                              void* d_out, int out_size) {
    const float* x_t      = (const float*)d_in[0];
    const float* h_lstm   = (const float*)d_in[1];
    const float* c_lstm   = (const float*)d_in[2];
    const float* slots    = (const float*)d_in[4];
    const float* cum      = (const float*)d_in[5];
    const float* delta    = (const float*)d_in[6];
    const void*  filled   = (const void*)d_in[7];
    const float* Wq       = (const float*)d_in[8];
    const float* Wk       = (const float*)d_in[9];
    const float* Wv       = (const float*)d_in[10];
    const float* bv       = (const float*)d_in[11];
    const float* lstm_Wih = (const float*)d_in[12];
    const float* lstm_Whh = (const float*)d_in[13];
    const float* lstm_bih = (const float*)d_in[14];
    const float* lstm_bhh = (const float*)d_in[15];
    const float* W_ih     = (const float*)d_in[16];
    const float* b_ih     = (const float*)d_in[17];
    const float* W_hh     = (const float*)d_in[18];
    float* out = (float*)d_out;

    float *p_kq, *p_v, *p_c, *p_bias, *p_biaso;
    __half *p_qh, *p_mem, *p_wstep, *p_wout, *p_xh, *p_hlh, *p_wqh, *p_wkT, *p_wvh;
    __half *p_h0, *p_h1;
    cudaGetSymbolAddress((void**)&p_qh, g_qh);
    cudaGetSymbolAddress((void**)&p_kq, g_kq);
    cudaGetSymbolAddress((void**)&p_v, g_v);
    cudaGetSymbolAddress((void**)&p_mem, g_mem);
    cudaGetSymbolAddress((void**)&p_c, g_c);
    cudaGetSymbolAddress((void**)&p_bias, g_bias);
    cudaGetSymbolAddress((void**)&p_biaso, g_biaso);
    cudaGetSymbolAddress((void**)&p_wstep, g_wstep);
    cudaGetSymbolAddress((void**)&p_wout, g_wout);
    cudaGetSymbolAddress((void**)&p_xh, g_xh);
    cudaGetSymbolAddress((void**)&p_hlh, g_hlh);
    cudaGetSymbolAddress((void**)&p_wqh, g_wqh);
    cudaGetSymbolAddress((void**)&p_wkT, g_wkT);
    cudaGetSymbolAddress((void**)&p_wvh, g_wvh);
    cudaGetSymbolAddress((void**)&p_h0, g_h0);
    cudaGetSymbolAddress((void**)&p_h1, g_h1);

    static int attr_set = 0;
    if (!attr_set) {
        cudaFuncSetAttribute(mma_gemm_kernel,
                             cudaFuncAttributeMaxDynamicSharedMemorySize, SMEM_DYN);
        cudaFuncSetAttribute(chain_kernel,
                             cudaFuncAttributeMaxDynamicSharedMemorySize, SMEM_DYN);
        attr_set = 1;
    }

    detect_filled_kernel<<<1, 256>>>((const unsigned int*)filled);
    zero_hc_kernel<<<(BB * HH + 255) / 256, 256>>>();
    prep_kernel<<<(unsigned)((Q8 + 255) / 256), 256>>>(
        lstm_Wih, lstm_Whh, lstm_bih, lstm_bhh,
        W_ih, W_hh, b_ih, x_t, h_lstm, Wq, Wk, Wv);

    GArgs a;
    // q = x @ Wq.T (fp16 store)
    a = {}; a.K = 256; a.ldw = 256; a.ldc = 512;
    a.s = { p_xh, nullptr, nullptr, 256, 0, 0, 256, 256 };
    a.W = p_wqh; a.Ch = p_qh;
    launch_g(a, BB, HH);
    // kq = q @ Wk
    a = {}; a.K = 512; a.ldw = 512; a.ldc = 256;
    a.s = { p_qh, nullptr, nullptr, 512, 0, 0, 512, 512 };
    a.W = p_wkT; a.C = p_kq;
    launch_g(a, BB, DD);
    // v = x @ Wv.T + bv
    a = {}; a.K = 256; a.ldw = 256; a.ldc = 256;
    a.s = { p_xh, nullptr, nullptr, 256, 0, 0, 256, 256 };
    a.W = p_wvh; a.bias = bv; a.C = p_v;
    launch_g(a, BB, DD);

    select_idx_kernel<<<BB, NSLOT>>>(slots, filled);
    {
        size_t tot = (size_t)BB * NSLOT * DD;
        update_write_kernel<<<(unsigned)((tot + 255) / 256), 256>>>(
            slots, cum, delta, filled, x_t, out);
    }

    // persistent slot-LSTM chain: all 64 steps in one launch
    {
        ChainArgs ca;
        ca.mem = p_mem; ca.W = p_wstep; ca.bias = p_bias;
        ca.h0 = p_h0; ca.h1 = p_h1; ca.c = p_c;
        ca.hmem_out = out + OFF_HMEM;
        chain_kernel<<<256, 256, SMEM_DYN>>>(ca);
    }

    // outer LSTM: K = [x(256) | h_mem(512) | h_lstm(512)]
    a = {}; a.lstm = 1; a.K = KOUT; a.ldw = KOUT; a.ldc = G4;
    a.s = { p_xh, p_h0, p_hlh, 256, 512, 512, 256, 768 };   // n=63 odd -> h in p_h0
    a.W = p_wout; a.bias = p_biaso;
    a.c_in = c_lstm; a.c_out = out + OFF_C; a.h_full = out + OFF_H;
    launch_g(a, BB, G4);
}

// round 13
// speedup vs baseline: 1.9105x; 1.0801x over previous
#include <cuda_runtime.h>
#include <cuda_fp16.h>
#include <math.h>
#include <stdint.h>

#define BB    2048
#define DD    256
#define HH    512
#define NSLOT 64
#define FEAT  513
#define FEATP 576           // padded to multiple of 64
#define G4    2048
#define KSTEP 1088          // 512 (h) + 576 (mem)
#define KOUT  1280          // 256 (x) + 512 (h_mem) + 512 (h_lstm)

#define OFF_H      ((size_t)0)
#define OFF_C      ((size_t)1048576)
#define OFF_HMEM   ((size_t)2097152)
#define OFF_SLOTS  ((size_t)3145728)
#define OFF_CUM    ((size_t)36700160)
#define OFF_DELTA  ((size_t)70254592)
#define OFF_FILLED ((size_t)70385664)

// ------------------------------- scratch ------------------------------------
__device__ __half g_qh[BB * HH];
__device__ float  g_kq[BB * DD];
__device__ float  g_v[BB * DD];
__device__ int    g_idx[BB];
__device__ float  g_bias[G4];
__device__ float  g_biaso[G4];
__device__ __half g_wstep[(size_t)G4 * KSTEP];
__device__ __half g_wout[(size_t)G4 * KOUT];
__device__ __half g_xh[BB * DD];
__device__ __half g_hlh[BB * HH];
__device__ __half g_wqh[HH * DD];
__device__ __half g_wkT[DD * HH];
__device__ __half g_wvh[DD * DD];
__device__ __half g_mem[(size_t)NSLOT * BB * FEATP];
__device__ __half g_h0[BB * HH];
__device__ __half g_h1[BB * HH];
__device__ float  g_c[BB * HH];
__device__ int    g_barc[NSLOT];          // chain barrier counters
__device__ int    g_fmode;

__device__ __forceinline__ float sigf(float x) { return 1.0f / (1.0f + __expf(-x)); }
__device__ __forceinline__ float tanh_fast(float x) {
    float t = __expf(-2.0f * fabsf(x));
    float r = (1.0f - t) / (1.0f + t);
    return copysignf(r, x);
}

__device__ __forceinline__ int read_filled(const void* p, size_t i, int m) {
    if (m == 0) return ((const float*)p)[i] != 0.0f;
    if (m == 1) return ((const int*)p)[i] != 0;
    if (m == 2) return ((const unsigned char*)p)[i] != 0;
    return ((const unsigned short*)p)[i] != 0;
}

// ----------------------------- PTX helpers ----------------------------------
__device__ __forceinline__ uint32_t smem_u32(const void* p) {
    uint32_t a;
    asm("{ .reg .u64 t; cvta.to.shared.u64 t, %1; cvt.u32.u64 %0, t; }" : "=r"(a) : "l"(p));
    return a;
}
__device__ __forceinline__ void cpasync16(uint32_t dst, const void* src) {
    asm volatile("cp.async.cg.shared.global [%0], [%1], 16;\n" :: "r"(dst), "l"(src));
}
#define CP_COMMIT() asm volatile("cp.async.commit_group;\n" ::: "memory")
#define CP_WAIT1()  asm volatile("cp.async.wait_group 1;\n" ::: "memory")

__device__ __forceinline__ void mma16(float* c, const uint32_t* A, const uint32_t* B) {
    asm volatile(
        "mma.sync.aligned.m16n8k16.row.col.f32.f16.f16.f32 "
        "{%0,%1,%2,%3}, {%4,%5,%6,%7}, {%8,%9}, {%0,%1,%2,%3};"
        : "+f"(c[0]), "+f"(c[1]), "+f"(c[2]), "+f"(c[3])
        : "r"(A[0]), "r"(A[1]), "r"(A[2]), "r"(A[3]), "r"(B[0]), "r"(B[1]));
}
__device__ __forceinline__ void ldsm4(uint32_t* r, uint32_t addr) {
    asm volatile("ldmatrix.sync.aligned.m8n8.x4.shared.b16 {%0,%1,%2,%3}, [%4];"
                 : "=r"(r[0]), "=r"(r[1]), "=r"(r[2]), "=r"(r[3]) : "r"(addr));
}

// ------------------------- fp16 warp-MMA GEMM core --------------------------
#define PADH 72                              // 64 data halfs + 8 pad (LDSM conflict-free)
#define TILE_HALFS (128 * PADH)              // 9216
#define BUF_HALFS  (2 * TILE_HALFS)          // 18432 halfs = 36864 B
#define SMEM_DYN   (3 * BUF_HALFS * 2)       // 110592 B

struct Seg {                                  // segmented A operand (<=3 pieces)
    const __half *p0, *p1, *p2;
    int l0, l1, l2, e0, e1;
};

__device__ __forceinline__ void load_stage64(uint32_t smb, const Seg& s,
                                             const __half* W, int ldw,
                                             int bm, int bn, int k0, int tid, int buf) {
    const uint32_t base = smb + (uint32_t)buf * BUF_HALFS * 2;
    const __half* Ap; int lda, ka;
    if (k0 < s.e0)      { Ap = s.p0; lda = s.l0; ka = k0; }
    else if (k0 < s.e1) { Ap = s.p1; lda = s.l1; ka = k0 - s.e0; }
    else                { Ap = s.p2; lda = s.l2; ka = k0 - s.e1; }
#pragma unroll
    for (int i = 0; i < 4; i++) {
        int idx = tid + i * 256;
        int r = idx >> 3, c = idx & 7;
        cpasync16(base + (uint32_t)(r * PADH + c * 8) * 2,
                  Ap + (size_t)(bm + r) * lda + ka + c * 8);
    }
#pragma unroll
    for (int i = 0; i < 4; i++) {
        int idx = tid + i * 256;
        int r = idx >> 3, c = idx & 7;
        cpasync16(base + (TILE_HALFS + (uint32_t)(r * PADH + c * 8)) * 2,
                  W + (size_t)(bn + r) * ldw + k0 + c * 8);
    }
}

__device__ __forceinline__ void gemm_loop(const __half* smh, uint32_t smb,
                                          const Seg& s, const __half* W, int ldw,
                                          int K, int bm, int bn, int tid,
                                          float acc[2][8][4]) {
    const int wid = tid >> 5, lane = tid & 31;
    const int wm = wid & 3, wn = wid >> 2;
#pragma unroll
    for (int mt = 0; mt < 2; mt++)
#pragma unroll
        for (int nt = 0; nt < 8; nt++)
#pragma unroll
            for (int e = 0; e < 4; e++) acc[mt][nt][e] = 0.0f;

    // ldmatrix per-lane byte offsets within a stage
    // A: row = r0 + (lane & 15), col(halfs) = 8 * (lane >> 4)
    const uint32_t offA0 = ((uint32_t)((wm * 32 + (lane & 15)) * PADH + 8 * (lane >> 4))) * 2;
    const uint32_t offA1 = offA0 + (uint32_t)(16 * PADH) * 2;
    // B: row = n0 + (lane & 7) + 8*(lane>>4), col(halfs) = 8 * ((lane>>3)&1)
    const int lbrow = (lane & 7) + ((lane >> 4) << 3);
    const int lbcol = ((lane >> 3) & 1) * 8;
    uint32_t offB[4];
#pragma unroll
    for (int p = 0; p < 4; p++)
        offB[p] = (uint32_t)(TILE_HALFS + (wn * 64 + p * 16 + lbrow) * PADH + lbcol) * 2;

    const int KT = K >> 6;
    load_stage64(smb, s, W, ldw, bm, bn, 0, tid, 0);
    CP_COMMIT();
    if (KT > 1) load_stage64(smb, s, W, ldw, bm, bn, 64, tid, 1);
    CP_COMMIT();

    for (int kt = 0; kt < KT; kt++) {
        CP_WAIT1();
        __syncthreads();
        if (kt + 2 < KT)
            load_stage64(smb, s, W, ldw, bm, bn, (kt + 2) * 64, tid, (kt + 2) % 3);
        CP_COMMIT();

        const uint32_t stage = smb + (uint32_t)(kt % 3) * BUF_HALFS * 2;
#pragma unroll
        for (int blk = 0; blk < 4; blk++) {
            const uint32_t kboff = (uint32_t)blk * 32;   // 16 halfs = 32 bytes
            uint32_t af[2][4];
            ldsm4(af[0], stage + offA0 + kboff);
            ldsm4(af[1], stage + offA1 + kboff);
            uint32_t bf[8][2];
#pragma unroll
            for (int p = 0; p < 4; p++) {
                uint32_t t4[4];
                ldsm4(t4, stage + offB[p] + kboff);
                bf[2 * p][0] = t4[0]; bf[2 * p][1] = t4[1];
                bf[2 * p + 1][0] = t4[2]; bf[2 * p + 1][1] = t4[3];
            }
#pragma unroll
            for (int mt = 0; mt < 2; mt++)
#pragma unroll
                for (int nt = 0; nt < 8; nt++)
                    mma16(acc[mt][nt], af[mt], bf[nt]);
        }
        __syncthreads();
    }
}

// fused LSTM pointwise epilogue (gate columns permuted 4j+t)
__device__ __forceinline__ void lstm_epilogue(float acc[2][8][4], float* gsm,
                                              const float* bias, const float* c_in,
                                              float* c_out, float* h_full, __half* h_tf,
                                              int bm, int bn, int tid) {
    const int wid = tid >> 5, lane = tid & 31;
    const int wm = wid & 3, wn = wid >> 2;
    const int gid = lane >> 2, tg = lane & 3;
#pragma unroll
    for (int mt = 0; mt < 2; mt++) {
        const int lr0 = wm * 32 + mt * 16 + gid;
        const int lr1 = lr0 + 8;
#pragma unroll
        for (int nt = 0; nt < 8; nt++) {
            const int lc = wn * 64 + nt * 8 + tg * 2;
            float2 v0 = make_float2(acc[mt][nt][0], acc[mt][nt][1]);
            float2 v1 = make_float2(acc[mt][nt][2], acc[mt][nt][3]);
            float2 b2 = *(const float2*)(bias + bn + lc);
            v0.x += b2.x; v0.y += b2.y; v1.x += b2.x; v1.y += b2.y;
            *(float2*)&gsm[lr0 * 132 + lc] = v0;
            *(float2*)&gsm[lr1 * 132 + lc] = v1;
        }
    }
    __syncthreads();
    const int jb = bn >> 2;
#pragma unroll
    for (int it = 0; it < 16; it++) {
        int idx = tid + it * 256;
        int row = idx >> 5, u = idx & 31;
        float4 gt = *(float4*)&gsm[row * 132 + 4 * u];
        float ii = sigf(gt.x), ff = sigf(gt.y);
        float gg = tanh_fast(gt.z), oo = sigf(gt.w);
        size_t e = (size_t)(bm + row) * HH + jb + u;
        float c_new = ff * c_in[e] + ii * gg;
        float h_new = oo * tanh_fast(c_new);
        c_out[e] = c_new;
        if (h_full) h_full[e] = h_new;
        if (h_tf)   h_tf[e] = __float2half_rn(h_new);
    }
}

// ---------------------- persistent slot-LSTM chain kernel -------------------
struct ChainArgs {
    const __half *mem, *W;
    const float *bias;
    __half *h0, *h1;
    float *c, *hmem_out;
};

__global__ void __launch_bounds__(256, 2) chain_kernel(const ChainArgs ca) {
    extern __shared__ __half smh[];
    const uint32_t smb = smem_u32(smh);
    const int tid = threadIdx.x;
    const int bm = (blockIdx.x >> 4) * 128;
    const int bn = (blockIdx.x & 15) * 128;
    float acc[2][8][4];

    for (int n = 0; n < NSLOT; n++) {
        Seg s;
        s.p0 = (n & 1) ? ca.h1 : ca.h0; s.l0 = HH; s.e0 = HH;
        s.p1 = ca.mem + (size_t)n * BB * FEATP; s.l1 = FEATP; s.e1 = KSTEP;
        s.p2 = nullptr; s.l2 = 0;
        gemm_loop(smh, smb, s, ca.W, KSTEP, KSTEP, bm, bn, tid, acc);

        lstm_epilogue(acc, (float*)smh, ca.bias, ca.c, ca.c,
                      (n == NSLOT - 1) ? ca.hmem_out : nullptr,
                      (n & 1) ? ca.h0 : ca.h1, bm, bn, tid);

        // grid-wide barrier: release h/c writes, arrive, spin, acquire
        __threadfence();
        __syncthreads();
        if (tid == 0) {
            atomicAdd(&g_barc[n], 1);
            volatile int* bp = &g_barc[n];
            while (*bp < 256) __nanosleep(64);
        }
        __syncthreads();
        __threadfence();
    }
}

// ------------------------- standalone GEMM kernel ----------------------------
struct GArgs {
    int lstm, K, ldw, ldc;
    Seg s;
    const __half *W;
    const float *bias, *c_in;
    float *C, *c_out, *h_full;
    __half *Ch;
};

__global__ void __launch_bounds__(256, 2) mma_gemm_kernel(const GArgs a) {
    extern __shared__ __half smh[];
    const uint32_t smb = smem_u32(smh);
    const int tid = threadIdx.x;
    const int wid = tid >> 5, lane = tid & 31;
    const int wm = wid & 3, wn = wid >> 2;
    const int gid = lane >> 2, tg = lane & 3;
    const int bm = blockIdx.y * 128;
    const int bn = blockIdx.x * 128;
    float acc[2][8][4];

    gemm_loop(smh, smb, a.s, a.W, a.ldw, a.K, bm, bn, tid, acc);

    if (a.lstm) {
        lstm_epilogue(acc, (float*)smh, a.bias, a.c_in, a.c_out, a.h_full,
                      nullptr, bm, bn, tid);
        return;
    }
#pragma unroll
    for (int mt = 0; mt < 2; mt++) {
        const size_t r0 = (size_t)bm + wm * 32 + mt * 16 + gid;
        const size_t r1 = r0 + 8;
#pragma unroll
        for (int nt = 0; nt < 8; nt++) {
            const int col = bn + wn * 64 + nt * 8 + tg * 2;
            float2 v0 = make_float2(acc[mt][nt][0], acc[mt][nt][1]);
            float2 v1 = make_float2(acc[mt][nt][2], acc[mt][nt][3]);
            if (a.bias) {
                float2 b2 = *(const float2*)(a.bias + col);
                v0.x += b2.x; v0.y += b2.y; v1.x += b2.x; v1.y += b2.y;
            }
            if (a.Ch) {
                *(__half2*)(a.Ch + r0 * a.ldc + col) = __floats2half2_rn(v0.x, v0.y);
                *(__half2*)(a.Ch + r1 * a.ldc + col) = __floats2half2_rn(v1.x, v1.y);
            } else {
                *(float2*)(a.C + r0 * a.ldc + col) = v0;
                *(float2*)(a.C + r1 * a.ldc + col) = v1;
            }
        }
    }
}

static void launch_g(const GArgs& a, int M, int N) {
    dim3 grid(N / 128, M / 128);
    mma_gemm_kernel<<<grid, 256, SMEM_DYN>>>(a);
}

// ------------------------------ prep kernels --------------------------------
__device__ __forceinline__ int porig(int p) { return ((p & 3) << 9) | (p >> 2); }

#define Q0 ((size_t)G4 * KSTEP)
#define Q1 (Q0 + (size_t)G4 * KOUT)
#define Q2 (Q1 + (size_t)BB * DD)
#define Q3 (Q2 + (size_t)BB * HH)
#define Q4 (Q3 + (size_t)HH * DD)
#define Q5 (Q4 + (size_t)DD * HH)
#define Q6 (Q5 + (size_t)DD * DD)
#define Q7 (Q6 + G4)
#define Q8 (Q7 + G4)

__global__ void prep_kernel(const float* __restrict__ Wih, const float* __restrict__ Whh,
                            const float* __restrict__ bih, const float* __restrict__ bhh,
                            const float* __restrict__ Wiho, const float* __restrict__ Whho,
                            const float* __restrict__ biho,
                            const float* __restrict__ x, const float* __restrict__ hl,
                            const float* __restrict__ Wq, const float* __restrict__ Wk,
                            const float* __restrict__ Wv) {
    size_t e = (size_t)blockIdx.x * blockDim.x + threadIdx.x;
    if (e < Q0) {
        int p = (int)(e / KSTEP), k = (int)(e % KSTEP);
        float v;
        if (k < 512) v = Whh[(size_t)porig(p) * 512 + k];
        else { int f = k - 512; v = (f < FEAT) ? Wih[(size_t)porig(p) * FEAT + f] : 0.0f; }
        g_wstep[e] = __float2half_rn(v);
    } else if (e < Q1) {
        size_t i = e - Q0; int p = (int)(i / KOUT), k = (int)(i % KOUT);
        float v = (k < 768) ? Wiho[(size_t)porig(p) * 768 + k]
                            : Whho[(size_t)porig(p) * 512 + (k - 768)];
        g_wout[i] = __float2half_rn(v);
    } else if (e < Q2) {
        size_t i = e - Q1; g_xh[i] = __float2half_rn(x[i]);
    } else if (e < Q3) {
        size_t i = e - Q2; g_hlh[i] = __float2half_rn(hl[i]);
    } else if (e < Q4) {
        size_t i = e - Q3; g_wqh[i] = __float2half_rn(Wq[i]);
    } else if (e < Q5) {
        size_t i = e - Q4; size_t d = i >> 9, h = i & 511;
        g_wkT[i] = __float2half_rn(Wk[h * 256 + d]);
    } else if (e < Q6) {
        size_t i = e - Q5; g_wvh[i] = __float2half_rn(Wv[i]);
    } else if (e < Q7) {
        int p = (int)(e - Q6); int o = porig(p);
        g_bias[p] = bih[o] + bhh[o];
    } else if (e < Q8) {
        int p = (int)(e - Q7);
        g_biaso[p] = biho[porig(p)];
    }
}

__global__ void zero_hc_kernel() {
    int e = blockIdx.x * blockDim.x + threadIdx.x;
    if (e < BB * HH) { g_h0[e] = __float2half_rn(0.0f); g_c[e] = 0.0f; }
    if (e < NSLOT) g_barc[e] = 0;
}

__global__ void detect_filled_kernel(const unsigned int* __restrict__ w) {
    __shared__ int flags[3];
    if (threadIdx.x < 3) flags[threadIdx.x] = 0;
    __syncthreads();
    for (int i = threadIdx.x; i < (BB * NSLOT) / 4; i += blockDim.x) {
        unsigned v = w[i];
        if (v == 0x3F800000u)      atomicOr(&flags[0], 1);
        else if (v == 0x3F803F80u) atomicOr(&flags[1], 1);
        else if (v > 1u)           atomicOr(&flags[2], 1);
    }
    __syncthreads();
    if (threadIdx.x == 0) {
        int m;
        if (flags[1])      m = 3;
        else if (flags[0]) m = 0;
        else if (flags[2]) m = 2;
        else               m = 1;
        g_fmode = m;
    }
}

__global__ void select_idx_kernel(const float* __restrict__ slots,
                                  const void* __restrict__ filled) {
    const int b = blockIdx.x;
    const int t = threadIdx.x;
    __shared__ float kq_s[DD];
    __shared__ float sims[NSLOT];
    __shared__ int   emp[NSLOT];
    for (int d = t; d < DD; d += NSLOT) kq_s[d] = g_kq[b * DD + d];
    __syncthreads();
    const float* sp = slots + ((size_t)b * NSLOT + t) * DD;
    float s = 0.0f;
    for (int d = 0; d < DD; d++) s = fmaf(sp[d], kq_s[d], s);
    sims[t] = s;
    emp[t]  = !read_filled(filled, (size_t)b * NSLOT + t, g_fmode);
    __syncthreads();
    if (t == 0) {
        int idx = -1;
        for (int n = 0; n < NSLOT; n++) if (emp[n]) { idx = n; break; }
        if (idx < 0) {
            float best = sims[0]; idx = 0;
            for (int n = 1; n < NSLOT; n++) if (sims[n] > best) { best = sims[n]; idx = n; }
        }
        g_idx[b] = idx;
    }
}

__global__ void update_write_kernel(const float* __restrict__ slots,
                                    const float* __restrict__ cum,
                                    const float* __restrict__ delta,
                                    const void* __restrict__ filled,
                                    const float* __restrict__ x,
                                    float* __restrict__ out) {
    size_t e = (size_t)blockIdx.x * blockDim.x + threadIdx.x;
    if (e >= (size_t)BB * NSLOT * DD) return;
    int d = (int)(e % DD);
    size_t bn = e / DD;
    int n = (int)(bn % NSLOT);
    int b = (int)(bn / NSLOT);
    int idx = g_idx[b];

    float xv = x[b * DD + d];
    float sl = slots[e];
    float cf = cum[e] + xv;
    if (n == idx) { sl = g_v[b * DD + d]; cf = xv; }

    out[OFF_SLOTS + e] = sl;
    out[OFF_CUM + e]   = cf;

    size_t mbase = ((size_t)n * BB + b) * FEATP;
    g_mem[mbase + d]      = __float2half_rn(sl);
    g_mem[mbase + DD + d] = __float2half_rn(cf);
    if (d < FEATP - FEAT) g_mem[mbase + FEAT + d] = __float2half_rn(0.0f);
    if (d == 0) {
        float dt = (n == idx) ? 0.0f : delta[bn] + 1.0f;
        out[OFF_DELTA + bn] = dt;
        g_mem[mbase + 2 * DD] = __float2half_rn(dt);
        int fl = (n == idx) ? 1 : read_filled(filled, bn, g_fmode);
        out[OFF_FILLED + bn] = fl ? 1.0f : 0.0f;
    }
}

// --------------------------------- launch -----------------------------------
extern "C" void kernel_launch(void* const* d_in, const int* in_sizes, int n_in,
                              void* d_out, int out_size) {
    const float* x_t      = (const float*)d_in[0];
    const float* h_lstm   = (const float*)d_in[1];
    const float* c_lstm   = (const float*)d_in[2];
    const float* slots    = (const float*)d_in[4];
    const float* cum      = (const float*)d_in[5];
    const float* delta    = (const float*)d_in[6];
    const void*  filled   = (const void*)d_in[7];
    const float* Wq       = (const float*)d_in[8];
    const float* Wk       = (const float*)d_in[9];
    const float* Wv       = (const float*)d_in[10];
    const float* bv       = (const float*)d_in[11];
    const float* lstm_Wih = (const float*)d_in[12];
    const float* lstm_Whh = (const float*)d_in[13];
    const float* lstm_bih = (const float*)d_in[14];
    const float* lstm_bhh = (const float*)d_in[15];
    const float* W_ih     = (const float*)d_in[16];
    const float* b_ih     = (const float*)d_in[17];
    const float* W_hh     = (const float*)d_in[18];
    float* out = (float*)d_out;

    float *p_kq, *p_v, *p_c, *p_bias, *p_biaso;
    __half *p_qh, *p_mem, *p_wstep, *p_wout, *p_xh, *p_hlh, *p_wqh, *p_wkT, *p_wvh;
    __half *p_h0, *p_h1;
    cudaGetSymbolAddress((void**)&p_qh, g_qh);
    cudaGetSymbolAddress((void**)&p_kq, g_kq);
    cudaGetSymbolAddress((void**)&p_v, g_v);
    cudaGetSymbolAddress((void**)&p_mem, g_mem);
    cudaGetSymbolAddress((void**)&p_c, g_c);
    cudaGetSymbolAddress((void**)&p_bias, g_bias);
    cudaGetSymbolAddress((void**)&p_biaso, g_biaso);
    cudaGetSymbolAddress((void**)&p_wstep, g_wstep);
    cudaGetSymbolAddress((void**)&p_wout, g_wout);
    cudaGetSymbolAddress((void**)&p_xh, g_xh);
    cudaGetSymbolAddress((void**)&p_hlh, g_hlh);
    cudaGetSymbolAddress((void**)&p_wqh, g_wqh);
    cudaGetSymbolAddress((void**)&p_wkT, g_wkT);
    cudaGetSymbolAddress((void**)&p_wvh, g_wvh);
    cudaGetSymbolAddress((void**)&p_h0, g_h0);
    cudaGetSymbolAddress((void**)&p_h1, g_h1);

    static int attr_set = 0;
    if (!attr_set) {
        cudaFuncSetAttribute(mma_gemm_kernel,
                             cudaFuncAttributeMaxDynamicSharedMemorySize, SMEM_DYN);
        cudaFuncSetAttribute(chain_kernel,
                             cudaFuncAttributeMaxDynamicSharedMemorySize, SMEM_DYN);
        attr_set = 1;
    }

    detect_filled_kernel<<<1, 256>>>((const unsigned int*)filled);
    zero_hc_kernel<<<(BB * HH + 255) / 256, 256>>>();
    prep_kernel<<<(unsigned)((Q8 + 255) / 256), 256>>>(
        lstm_Wih, lstm_Whh, lstm_bih, lstm_bhh,
        W_ih, W_hh, b_ih, x_t, h_lstm, Wq, Wk, Wv);

    GArgs a;
    // q = x @ Wq.T (fp16 store)
    a = {}; a.K = 256; a.ldw = 256; a.ldc = 512;
    a.s = { p_xh, nullptr, nullptr, 256, 0, 0, 256, 256 };
    a.W = p_wqh; a.Ch = p_qh;
    launch_g(a, BB, HH);
    // kq = q @ Wk
    a = {}; a.K = 512; a.ldw = 512; a.ldc = 256;
    a.s = { p_qh, nullptr, nullptr, 512, 0, 0, 512, 512 };
    a.W = p_wkT; a.C = p_kq;
    launch_g(a, BB, DD);
    // v = x @ Wv.T + bv
    a = {}; a.K = 256; a.ldw = 256; a.ldc = 256;
    a.s = { p_xh, nullptr, nullptr, 256, 0, 0, 256, 256 };
    a.W = p_wvh; a.bias = bv; a.C = p_v;
    launch_g(a, BB, DD);

    select_idx_kernel<<<BB, NSLOT>>>(slots, filled);
    {
        size_t tot = (size_t)BB * NSLOT * DD;
        update_write_kernel<<<(unsigned)((tot + 255) / 256), 256>>>(
            slots, cum, delta, filled, x_t, out);
    }

    // persistent slot-LSTM chain: all 64 steps in one launch
    {
        ChainArgs ca;
        ca.mem = p_mem; ca.W = p_wstep; ca.bias = p_bias;
        ca.h0 = p_h0; ca.h1 = p_h1; ca.c = p_c;
        ca.hmem_out = out + OFF_HMEM;
        chain_kernel<<<256, 256, SMEM_DYN>>>(ca);
    }

    // outer LSTM: K = [x(256) | h_mem(512) | h_lstm(512)]
    a = {}; a.lstm = 1; a.K = KOUT; a.ldw = KOUT; a.ldc = G4;
    a.s = { p_xh, p_h0, p_hlh, 256, 512, 512, 256, 768 };   // n=63 odd -> h in p_h0
    a.W = p_wout; a.bias = p_biaso;
    a.c_in = c_lstm; a.c_out = out + OFF_C; a.h_full = out + OFF_H;
    launch_g(a, BB, G4);
}

// round 14
// speedup vs baseline: 2.0407x; 1.0682x over previous
#include <cuda_runtime.h>
#include <cuda_fp16.h>
#include <math.h>
#include <stdint.h>

#define BB    2048
#define DD    256
#define HH    512
#define NSLOT 64
#define FEAT  513
#define FEATP 576           // padded to multiple of 64
#define G4    2048
#define KSTEP 1088          // 512 (h) + 576 (mem)
#define KOUT  1280          // 256 (x) + 512 (h_mem) + 512 (h_lstm)

#define OFF_H      ((size_t)0)
#define OFF_C      ((size_t)1048576)
#define OFF_HMEM   ((size_t)2097152)
#define OFF_SLOTS  ((size_t)3145728)
#define OFF_CUM    ((size_t)36700160)
#define OFF_DELTA  ((size_t)70254592)
#define OFF_FILLED ((size_t)70385664)

// ------------------------------- scratch ------------------------------------
__device__ __half g_qh[BB * HH];
__device__ float  g_kq[BB * DD];
__device__ float  g_v[BB * DD];
__device__ int    g_idx[BB];
__device__ float  g_bias[G4];
__device__ float  g_biaso[G4];
__device__ __half g_wstep[(size_t)G4 * KSTEP];
__device__ __half g_wout[(size_t)G4 * KOUT];
__device__ __half g_xh[BB * DD];
__device__ __half g_hlh[BB * HH];
__device__ __half g_wqh[HH * DD];
__device__ __half g_wkT[DD * HH];
__device__ __half g_wvh[DD * DD];
__device__ __half g_mem[(size_t)NSLOT * BB * FEATP];
__device__ __half g_h0[BB * HH];
__device__ __half g_h1[BB * HH];
__device__ float  g_c[BB * HH];
__device__ int    g_barc[NSLOT];          // chain barrier counters
__device__ int    g_fmode;

__device__ __forceinline__ float sigf(float x) { return 1.0f / (1.0f + __expf(-x)); }
__device__ __forceinline__ float tanh_fast(float x) {
    float t = __expf(-2.0f * fabsf(x));
    float r = (1.0f - t) / (1.0f + t);
    return copysignf(r, x);
}

__device__ __forceinline__ int read_filled(const void* p, size_t i, int m) {
    if (m == 0) return ((const float*)p)[i] != 0.0f;
    if (m == 1) return ((const int*)p)[i] != 0;
    if (m == 2) return ((const unsigned char*)p)[i] != 0;
    return ((const unsigned short*)p)[i] != 0;
}

// ----------------------------- PTX helpers ----------------------------------
__device__ __forceinline__ uint32_t smem_u32(const void* p) {
    uint32_t a;
    asm("{ .reg .u64 t; cvta.to.shared.u64 t, %1; cvt.u32.u64 %0, t; }" : "=r"(a) : "l"(p));
    return a;
}
__device__ __forceinline__ void cpasync16(uint32_t dst, const void* src) {
    asm volatile("cp.async.cg.shared.global [%0], [%1], 16;\n" :: "r"(dst), "l"(src));
}
#define CP_COMMIT() asm volatile("cp.async.commit_group;\n" ::: "memory")
#define CP_WAIT1()  asm volatile("cp.async.wait_group 1;\n" ::: "memory")

__device__ __forceinline__ void mma16(float* c, const uint32_t* A, const uint32_t* B) {
    asm volatile(
        "mma.sync.aligned.m16n8k16.row.col.f32.f16.f16.f32 "
        "{%0,%1,%2,%3}, {%4,%5,%6,%7}, {%8,%9}, {%0,%1,%2,%3};"
        : "+f"(c[0]), "+f"(c[1]), "+f"(c[2]), "+f"(c[3])
        : "r"(A[0]), "r"(A[1]), "r"(A[2]), "r"(A[3]), "r"(B[0]), "r"(B[1]));
}
__device__ __forceinline__ void ldsm4(uint32_t* r, uint32_t addr) {
    asm volatile("ldmatrix.sync.aligned.m8n8.x4.shared.b16 {%0,%1,%2,%3}, [%4];"
                 : "=r"(r[0]), "=r"(r[1]), "=r"(r[2]), "=r"(r[3]) : "r"(addr));
}

// ------------------------- fp16 warp-MMA GEMM core --------------------------
#define PADH 72                              // 64 data halfs + 8 pad (LDSM conflict-free)
#define TILE_HALFS (128 * PADH)              // 9216
#define BUF_HALFS  (2 * TILE_HALFS)          // 18432 halfs = 36864 B
#define SMEM_DYN   (3 * BUF_HALFS * 2)       // 110592 B

struct Seg {                                  // segmented A operand (<=3 pieces)
    const __half *p0, *p1, *p2;
    int l0, l1, l2, e0, e1;
};

__device__ __forceinline__ void load_stage64(uint32_t smb, const Seg& s,
                                             const __half* W, int ldw,
                                             int bm, int bn, int k0, int tid, int buf) {
    const uint32_t base = smb + (uint32_t)buf * BUF_HALFS * 2;
    const __half* Ap; int lda, ka;
    if (k0 < s.e0)      { Ap = s.p0; lda = s.l0; ka = k0; }
    else if (k0 < s.e1) { Ap = s.p1; lda = s.l1; ka = k0 - s.e0; }
    else                { Ap = s.p2; lda = s.l2; ka = k0 - s.e1; }
#pragma unroll
    for (int i = 0; i < 4; i++) {
        int idx = tid + i * 256;
        int r = idx >> 3, c = idx & 7;
        cpasync16(base + (uint32_t)(r * PADH + c * 8) * 2,
                  Ap + (size_t)(bm + r) * lda + ka + c * 8);
    }
#pragma unroll
    for (int i = 0; i < 4; i++) {
        int idx = tid + i * 256;
        int r = idx >> 3, c = idx & 7;
        cpasync16(base + (TILE_HALFS + (uint32_t)(r * PADH + c * 8)) * 2,
                  W + (size_t)(bn + r) * ldw + k0 + c * 8);
    }
}

// per-lane ldmatrix offsets (byte) within a stage
struct LdsmOff { uint32_t a0, a1, b[4]; };
__device__ __forceinline__ LdsmOff make_off(int tid) {
    const int wid = tid >> 5, lane = tid & 31;
    const int wm = wid & 3, wn = wid >> 2;
    LdsmOff o;
    o.a0 = ((uint32_t)((wm * 32 + (lane & 15)) * PADH + 8 * (lane >> 4))) * 2;
    o.a1 = o.a0 + (uint32_t)(16 * PADH) * 2;
    const int lbrow = (lane & 7) + ((lane >> 4) << 3);
    const int lbcol = ((lane >> 3) & 1) * 8;
#pragma unroll
    for (int p = 0; p < 4; p++)
        o.b[p] = (uint32_t)(TILE_HALFS + (wn * 64 + p * 16 + lbrow) * PADH + lbcol) * 2;
    return o;
}

__device__ __forceinline__ void compute_tile(uint32_t stage, const LdsmOff& o,
                                             float acc[2][8][4]) {
#pragma unroll
    for (int blk = 0; blk < 4; blk++) {
        const uint32_t kboff = (uint32_t)blk * 32;   // 16 halfs = 32 bytes
        uint32_t af[2][4];
        ldsm4(af[0], stage + o.a0 + kboff);
        ldsm4(af[1], stage + o.a1 + kboff);
        uint32_t bf[8][2];
#pragma unroll
        for (int p = 0; p < 4; p++) {
            uint32_t t4[4];
            ldsm4(t4, stage + o.b[p] + kboff);
            bf[2 * p][0] = t4[0]; bf[2 * p][1] = t4[1];
            bf[2 * p + 1][0] = t4[2]; bf[2 * p + 1][1] = t4[3];
        }
#pragma unroll
        for (int mt = 0; mt < 2; mt++)
#pragma unroll
            for (int nt = 0; nt < 8; nt++)
                mma16(acc[mt][nt], af[mt], bf[nt]);
    }
}

__device__ __forceinline__ void gemm_loop(uint32_t smb, const Seg& s,
                                          const __half* W, int ldw,
                                          int K, int bm, int bn, int tid,
                                          const LdsmOff& o, float acc[2][8][4]) {
#pragma unroll
    for (int mt = 0; mt < 2; mt++)
#pragma unroll
        for (int nt = 0; nt < 8; nt++)
#pragma unroll
            for (int e = 0; e < 4; e++) acc[mt][nt][e] = 0.0f;

    const int KT = K >> 6;
    load_stage64(smb, s, W, ldw, bm, bn, 0, tid, 0);
    CP_COMMIT();
    if (KT > 1) load_stage64(smb, s, W, ldw, bm, bn, 64, tid, 1);
    CP_COMMIT();

    for (int kt = 0; kt < KT; kt++) {
        CP_WAIT1();
        __syncthreads();
        if (kt + 2 < KT)
            load_stage64(smb, s, W, ldw, bm, bn, (kt + 2) * 64, tid, (kt + 2) % 3);
        CP_COMMIT();
        compute_tile(smb + (uint32_t)(kt % 3) * BUF_HALFS * 2, o, acc);
    }
    __syncthreads();   // guard smem reuse by epilogue
}

// fused LSTM pointwise epilogue (gate columns permuted 4j+t)
__device__ __forceinline__ void lstm_epilogue(float acc[2][8][4], float* gsm,
                                              const float* bias, const float* c_in,
                                              float* c_out, float* h_full, __half* h_tf,
                                              int bm, int bn, int tid) {
    const int wid = tid >> 5, lane = tid & 31;
    const int wm = wid & 3, wn = wid >> 2;
    const int gid = lane >> 2, tg = lane & 3;
#pragma unroll
    for (int mt = 0; mt < 2; mt++) {
        const int lr0 = wm * 32 + mt * 16 + gid;
        const int lr1 = lr0 + 8;
#pragma unroll
        for (int nt = 0; nt < 8; nt++) {
            const int lc = wn * 64 + nt * 8 + tg * 2;
            float2 v0 = make_float2(acc[mt][nt][0], acc[mt][nt][1]);
            float2 v1 = make_float2(acc[mt][nt][2], acc[mt][nt][3]);
            float2 b2 = *(const float2*)(bias + bn + lc);
            v0.x += b2.x; v0.y += b2.y; v1.x += b2.x; v1.y += b2.y;
            *(float2*)&gsm[lr0 * 132 + lc] = v0;
            *(float2*)&gsm[lr1 * 132 + lc] = v1;
        }
    }
    __syncthreads();
    const int jb = bn >> 2;
#pragma unroll
    for (int it = 0; it < 16; it++) {
        int idx = tid + it * 256;
        int row = idx >> 5, u = idx & 31;
        float4 gt = *(float4*)&gsm[row * 132 + 4 * u];
        float ii = sigf(gt.x), ff = sigf(gt.y);
        float gg = tanh_fast(gt.z), oo = sigf(gt.w);
        size_t e = (size_t)(bm + row) * HH + jb + u;
        float c_new = ff * c_in[e] + ii * gg;
        float h_new = oo * tanh_fast(c_new);
        c_out[e] = c_new;
        if (h_full) h_full[e] = h_new;
        if (h_tf)   h_tf[e] = __float2half_rn(h_new);
    }
}

// ---------------------- persistent slot-LSTM chain kernel -------------------
// Per step, k-tiles are ordered mem-first: tiles 0..8 cover mem (K 512..1088,
// no cross-step dependency), tiles 9..16 cover h (K 0..512). The grid barrier
// is arrive-only after the epilogue; the spin is deferred to iteration 7,
// right before the first h-tile load is issued, hiding barrier latency and
// inter-CTA skew behind the 9 mem tiles.
struct ChainArgs {
    const __half *mem, *W;
    const float *bias;
    __half *h0, *h1;
    float *c, *hmem_out;
};

__global__ void __launch_bounds__(256, 2) chain_kernel(const ChainArgs ca) {
    extern __shared__ __half smh[];
    const uint32_t smb = smem_u32(smh);
    const int tid = threadIdx.x;
    const int bm = (blockIdx.x >> 4) * 128;
    const int bn = (blockIdx.x & 15) * 128;
    const LdsmOff o = make_off(tid);
    float acc[2][8][4];
    const int KT = KSTEP >> 6;   // 17; tiles 0..8 = mem, 9..16 = h

    for (int n = 0; n < NSLOT; n++) {
        const __half* hbuf = (n & 1) ? ca.h1 : ca.h0;
        const __half* memn = ca.mem + (size_t)n * BB * FEATP;
#pragma unroll
        for (int mt = 0; mt < 2; mt++)
#pragma unroll
            for (int nt = 0; nt < 8; nt++)
#pragma unroll
                for (int e = 0; e < 4; e++) acc[mt][nt][e] = 0.0f;

        // tile i -> k0: i<9 mem (512+64i), else h (64*(i-9))
        auto ld = [&](int i, int buf) {
            int k0 = (i < 9) ? 512 + 64 * i : 64 * (i - 9);
            const __half* Ap = (k0 < 512) ? hbuf : memn;
            int lda = (k0 < 512) ? HH : FEATP;
            int ka  = (k0 < 512) ? k0 : k0 - 512;
            const uint32_t base = smb + (uint32_t)buf * BUF_HALFS * 2;
#pragma unroll
            for (int j = 0; j < 4; j++) {
                int idx = tid + j * 256;
                int r = idx >> 3, c2 = idx & 7;
                cpasync16(base + (uint32_t)(r * PADH + c2 * 8) * 2,
                          Ap + (size_t)(bm + r) * lda + ka + c2 * 8);
            }
#pragma unroll
            for (int j = 0; j < 4; j++) {
                int idx = tid + j * 256;
                int r = idx >> 3, c2 = idx & 7;
                cpasync16(base + (TILE_HALFS + (uint32_t)(r * PADH + c2 * 8)) * 2,
                          ca.W + (size_t)(bn + r) * KSTEP + k0 + c2 * 8);
            }
        };

        ld(0, 0); CP_COMMIT();
        ld(1, 1); CP_COMMIT();
        for (int i = 0; i < KT; i++) {
            CP_WAIT1();
            __syncthreads();
            if (i == 7 && n > 0) {            // before first h-tile load (i+2==9)
                if (tid == 0) {
                    volatile int* bp = &g_barc[n - 1];
                    while (*bp < 256) __nanosleep(64);
                }
                __syncthreads();
                __threadfence();
            }
            if (i + 2 < KT) ld(i + 2, (i + 2) % 3);
            CP_COMMIT();
            compute_tile(smb + (uint32_t)(i % 3) * BUF_HALFS * 2, o, acc);
        }
        __syncthreads();   // guard smem reuse by epilogue

        lstm_epilogue(acc, (float*)smh, ca.bias, ca.c, ca.c,
                      (n == NSLOT - 1) ? ca.hmem_out : nullptr,
                      (n & 1) ? ca.h0 : ca.h1, bm, bn, tid);

        // release h writes + guard gsm against next step's loads, then arrive
        __threadfence();
        __syncthreads();
        if (tid == 0) atomicAdd(&g_barc[n], 1);
    }
}

// ------------------------- standalone GEMM kernel ----------------------------
struct GArgs {
    int lstm, K, ldw, ldc;
    Seg s;
    const __half *W;
    const float *bias, *c_in;
    float *C, *c_out, *h_full;
    __half *Ch;
};

__global__ void __launch_bounds__(256, 2) mma_gemm_kernel(const GArgs a) {
    extern __shared__ __half smh[];
    const uint32_t smb = smem_u32(smh);
    const int tid = threadIdx.x;
    const int wid = tid >> 5, lane = tid & 31;
    const int wm = wid & 3, wn = wid >> 2;
    const int gid = lane >> 2, tg = lane & 3;
    const int bm = blockIdx.y * 128;
    const int bn = blockIdx.x * 128;
    const LdsmOff o = make_off(tid);
    float acc[2][8][4];

    gemm_loop(smb, a.s, a.W, a.ldw, a.K, bm, bn, tid, o, acc);

    if (a.lstm) {
        lstm_epilogue(acc, (float*)smh, a.bias, a.c_in, a.c_out, a.h_full,
                      nullptr, bm, bn, tid);
        return;
    }
#pragma unroll
    for (int mt = 0; mt < 2; mt++) {
        const size_t r0 = (size_t)bm + wm * 32 + mt * 16 + gid;
        const size_t r1 = r0 + 8;
#pragma unroll
        for (int nt = 0; nt < 8; nt++) {
            const int col = bn + wn * 64 + nt * 8 + tg * 2;
            float2 v0 = make_float2(acc[mt][nt][0], acc[mt][nt][1]);
            float2 v1 = make_float2(acc[mt][nt][2], acc[mt][nt][3]);
            if (a.bias) {
                float2 b2 = *(const float2*)(a.bias + col);
                v0.x += b2.x; v0.y += b2.y; v1.x += b2.x; v1.y += b2.y;
            }
            if (a.Ch) {
                *(__half2*)(a.Ch + r0 * a.ldc + col) = __floats2half2_rn(v0.x, v0.y);
                *(__half2*)(a.Ch + r1 * a.ldc + col) = __floats2half2_rn(v1.x, v1.y);
            } else {
                *(float2*)(a.C + r0 * a.ldc + col) = v0;
                *(float2*)(a.C + r1 * a.ldc + col) = v1;
            }
        }
    }
}

static void launch_g(const GArgs& a, int M, int N) {
    dim3 grid(N / 128, M / 128);
    mma_gemm_kernel<<<grid, 256, SMEM_DYN>>>(a);
}

// ------------------------------ prep kernels --------------------------------
__device__ __forceinline__ int porig(int p) { return ((p & 3) << 9) | (p >> 2); }

#define Q0 ((size_t)G4 * KSTEP)
#define Q1 (Q0 + (size_t)G4 * KOUT)
#define Q2 (Q1 + (size_t)BB * DD)
#define Q3 (Q2 + (size_t)BB * HH)
#define Q4 (Q3 + (size_t)HH * DD)
#define Q5 (Q4 + (size_t)DD * HH)
#define Q6 (Q5 + (size_t)DD * DD)
#define Q7 (Q6 + G4)
#define Q8 (Q7 + G4)

__global__ void prep_kernel(const float* __restrict__ Wih, const float* __restrict__ Whh,
                            const float* __restrict__ bih, const float* __restrict__ bhh,
                            const float* __restrict__ Wiho, const float* __restrict__ Whho,
                            const float* __restrict__ biho,
                            const float* __restrict__ x, const float* __restrict__ hl,
                            const float* __restrict__ Wq, const float* __restrict__ Wk,
                            const float* __restrict__ Wv) {
    size_t e = (size_t)blockIdx.x * blockDim.x + threadIdx.x;
    if (e < Q0) {
        int p = (int)(e / KSTEP), k = (int)(e % KSTEP);
        float v;
        if (k < 512) v = Whh[(size_t)porig(p) * 512 + k];
        else { int f = k - 512; v = (f < FEAT) ? Wih[(size_t)porig(p) * FEAT + f] : 0.0f; }
        g_wstep[e] = __float2half_rn(v);
    } else if (e < Q1) {
        size_t i = e - Q0; int p = (int)(i / KOUT), k = (int)(i % KOUT);
        float v = (k < 768) ? Wiho[(size_t)porig(p) * 768 + k]
                            : Whho[(size_t)porig(p) * 512 + (k - 768)];
        g_wout[i] = __float2half_rn(v);
    } else if (e < Q2) {
        size_t i = e - Q1; g_xh[i] = __float2half_rn(x[i]);
    } else if (e < Q3) {
        size_t i = e - Q2; g_hlh[i] = __float2half_rn(hl[i]);
    } else if (e < Q4) {
        size_t i = e - Q3; g_wqh[i] = __float2half_rn(Wq[i]);
    } else if (e < Q5) {
        size_t i = e - Q4; size_t d = i >> 9, h = i & 511;
        g_wkT[i] = __float2half_rn(Wk[h * 256 + d]);
    } else if (e < Q6) {
        size_t i = e - Q5; g_wvh[i] = __float2half_rn(Wv[i]);
    } else if (e < Q7) {
        int p = (int)(e - Q6); int o = porig(p);
        g_bias[p] = bih[o] + bhh[o];
    } else if (e < Q8) {
        int p = (int)(e - Q7);
        g_biaso[p] = biho[porig(p)];
    }
}

__global__ void zero_hc_kernel() {
    int e = blockIdx.x * blockDim.x + threadIdx.x;
    if (e < BB * HH) { g_h0[e] = __float2half_rn(0.0f); g_c[e] = 0.0f; }
    if (e < NSLOT) g_barc[e] = 0;
}

__global__ void detect_filled_kernel(const unsigned int* __restrict__ w) {
    __shared__ int flags[3];
    if (threadIdx.x < 3) flags[threadIdx.x] = 0;
    __syncthreads();
    for (int i = threadIdx.x; i < (BB * NSLOT) / 4; i += blockDim.x) {
        unsigned v = w[i];
        if (v == 0x3F800000u)      atomicOr(&flags[0], 1);
        else if (v == 0x3F803F80u) atomicOr(&flags[1], 1);
        else if (v > 1u)           atomicOr(&flags[2], 1);
    }
    __syncthreads();
    if (threadIdx.x == 0) {
        int m;
        if (flags[1])      m = 3;
        else if (flags[0]) m = 0;
        else if (flags[2]) m = 2;
        else               m = 1;
        g_fmode = m;
    }
}

__global__ void select_idx_kernel(const float* __restrict__ slots,
                                  const void* __restrict__ filled) {
    const int b = blockIdx.x;
    const int t = threadIdx.x;
    __shared__ float kq_s[DD];
    __shared__ float sims[NSLOT];
    __shared__ int   emp[NSLOT];
    for (int d = t; d < DD; d += NSLOT) kq_s[d] = g_kq[b * DD + d];
    __syncthreads();
    const float* sp = slots + ((size_t)b * NSLOT + t) * DD;
    float s = 0.0f;
    for (int d = 0; d < DD; d++) s = fmaf(sp[d], kq_s[d], s);
    sims[t] = s;
    emp[t]  = !read_filled(filled, (size_t)b * NSLOT + t, g_fmode);
    __syncthreads();
    if (t == 0) {
        int idx = -1;
        for (int n = 0; n < NSLOT; n++) if (emp[n]) { idx = n; break; }
        if (idx < 0) {
            float best = sims[0]; idx = 0;
            for (int n = 1; n < NSLOT; n++) if (sims[n] > best) { best = sims[n]; idx = n; }
        }
        g_idx[b] = idx;
    }
}

__global__ void update_write_kernel(const float* __restrict__ slots,
                                    const float* __restrict__ cum,
                                    const float* __restrict__ delta,
                                    const void* __restrict__ filled,
                                    const float* __restrict__ x,
                                    float* __restrict__ out) {
    size_t e = (size_t)blockIdx.x * blockDim.x + threadIdx.x;
    if (e >= (size_t)BB * NSLOT * DD) return;
    int d = (int)(e % DD);
    size_t bn = e / DD;
    int n = (int)(bn % NSLOT);
    int b = (int)(bn / NSLOT);
    int idx = g_idx[b];

    float xv = x[b * DD + d];
    float sl = slots[e];
    float cf = cum[e] + xv;
    if (n == idx) { sl = g_v[b * DD + d]; cf = xv; }

    out[OFF_SLOTS + e] = sl;
    out[OFF_CUM + e]   = cf;

    size_t mbase = ((size_t)n * BB + b) * FEATP;
    g_mem[mbase + d]      = __float2half_rn(sl);
    g_mem[mbase + DD + d] = __float2half_rn(cf);
    if (d < FEATP - FEAT) g_mem[mbase + FEAT + d] = __float2half_rn(0.0f);
    if (d == 0) {
        float dt = (n == idx) ? 0.0f : delta[bn] + 1.0f;
        out[OFF_DELTA + bn] = dt;
        g_mem[mbase + 2 * DD] = __float2half_rn(dt);
        int fl = (n == idx) ? 1 : read_filled(filled, bn, g_fmode);
        out[OFF_FILLED + bn] = fl ? 1.0f : 0.0f;
    }
}

// --------------------------------- launch -----------------------------------
extern "C" void kernel_launch(void* const* d_in, const int* in_sizes, int n_in,
                              void* d_out, int out_size) {
    const float* x_t      = (const float*)d_in[0];
    const float* h_lstm   = (const float*)d_in[1];
    const float* c_lstm   = (const float*)d_in[2];
    const float* slots    = (const float*)d_in[4];
    const float* cum      = (const float*)d_in[5];
    const float* delta    = (const float*)d_in[6];
    const void*  filled   = (const void*)d_in[7];
    const float* Wq       = (const float*)d_in[8];
    const float* Wk       = (const float*)d_in[9];
    const float* Wv       = (const float*)d_in[10];
    const float* bv       = (const float*)d_in[11];
    const float* lstm_Wih = (const float*)d_in[12];
    const float* lstm_Whh = (const float*)d_in[13];
    const float* lstm_bih = (const float*)d_in[14];
    const float* lstm_bhh = (const float*)d_in[15];
    const float* W_ih     = (const float*)d_in[16];
    const float* b_ih     = (const float*)d_in[17];
    const float* W_hh     = (const float*)d_in[18];
    float* out = (float*)d_out;

    float *p_kq, *p_v, *p_c, *p_bias, *p_biaso;
    __half *p_qh, *p_mem, *p_wstep, *p_wout, *p_xh, *p_hlh, *p_wqh, *p_wkT, *p_wvh;
    __half *p_h0, *p_h1;
    cudaGetSymbolAddress((void**)&p_qh, g_qh);
    cudaGetSymbolAddress((void**)&p_kq, g_kq);
    cudaGetSymbolAddress((void**)&p_v, g_v);
    cudaGetSymbolAddress((void**)&p_mem, g_mem);
    cudaGetSymbolAddress((void**)&p_c, g_c);
    cudaGetSymbolAddress((void**)&p_bias, g_bias);
    cudaGetSymbolAddress((void**)&p_biaso, g_biaso);
    cudaGetSymbolAddress((void**)&p_wstep, g_wstep);
    cudaGetSymbolAddress((void**)&p_wout, g_wout);
    cudaGetSymbolAddress((void**)&p_xh, g_xh);
    cudaGetSymbolAddress((void**)&p_hlh, g_hlh);
    cudaGetSymbolAddress((void**)&p_wqh, g_wqh);
    cudaGetSymbolAddress((void**)&p_wkT, g_wkT);
    cudaGetSymbolAddress((void**)&p_wvh, g_wvh);
    cudaGetSymbolAddress((void**)&p_h0, g_h0);
    cudaGetSymbolAddress((void**)&p_h1, g_h1);

    static int attr_set = 0;
    if (!attr_set) {
        cudaFuncSetAttribute(mma_gemm_kernel,
                             cudaFuncAttributeMaxDynamicSharedMemorySize, SMEM_DYN);
        cudaFuncSetAttribute(chain_kernel,
                             cudaFuncAttributeMaxDynamicSharedMemorySize, SMEM_DYN);
        attr_set = 1;
    }

    detect_filled_kernel<<<1, 256>>>((const unsigned int*)filled);
    zero_hc_kernel<<<(BB * HH + 255) / 256, 256>>>();
    prep_kernel<<<(unsigned)((Q8 + 255) / 256), 256>>>(
        lstm_Wih, lstm_Whh, lstm_bih, lstm_bhh,
        W_ih, W_hh, b_ih, x_t, h_lstm, Wq, Wk, Wv);

    GArgs a;
    // q = x @ Wq.T (fp16 store)
    a = {}; a.K = 256; a.ldw = 256; a.ldc = 512;
    a.s = { p_xh, nullptr, nullptr, 256, 0, 0, 256, 256 };
    a.W = p_wqh; a.Ch = p_qh;
    launch_g(a, BB, HH);
    // kq = q @ Wk
    a = {}; a.K = 512; a.ldw = 512; a.ldc = 256;
    a.s = { p_qh, nullptr, nullptr, 512, 0, 0, 512, 512 };
    a.W = p_wkT; a.C = p_kq;
    launch_g(a, BB, DD);
    // v = x @ Wv.T + bv
    a = {}; a.K = 256; a.ldw = 256; a.ldc = 256;
    a.s = { p_xh, nullptr, nullptr, 256, 0, 0, 256, 256 };
    a.W = p_wvh; a.bias = bv; a.C = p_v;
    launch_g(a, BB, DD);

    select_idx_kernel<<<BB, NSLOT>>>(slots, filled);
    {
        size_t tot = (size_t)BB * NSLOT * DD;
        update_write_kernel<<<(unsigned)((tot + 255) / 256), 256>>>(
            slots, cum, delta, filled, x_t, out);
    }

    // persistent slot-LSTM chain: all 64 steps in one launch, deferred barrier
    {
        ChainArgs ca;
        ca.mem = p_mem; ca.W = p_wstep; ca.bias = p_bias;
        ca.h0 = p_h0; ca.h1 = p_h1; ca.c = p_c;
        ca.hmem_out = out + OFF_HMEM;
        chain_kernel<<<256, 256, SMEM_DYN>>>(ca);
    }

    // outer LSTM: K = [x(256) | h_mem(512) | h_lstm(512)]
    a = {}; a.lstm = 1; a.K = KOUT; a.ldw = KOUT; a.ldc = G4;
    a.s = { p_xh, p_h0, p_hlh, 256, 512, 512, 256, 768 };   // n=63 odd -> h in p_h0
    a.W = p_wout; a.bias = p_biaso;
    a.c_in = c_lstm; a.c_out = out + OFF_C; a.h_full = out + OFF_H;
    launch_g(a, BB, G4);
}